// round 9
// baseline (speedup 1.0000x reference)
#include <cuda_runtime.h>
#include <cuda_bf16.h>
#include <cstdint>
#include <math.h>

// Problem constants
#define HWDIM 80
#define NPIX  6400
#define DIM   512
#define QKVN  1536
#define NHEAD 8
#define HD    64
#define KWIN  7

// Scratch (allocation-free rule: __device__ globals)
__device__ float g_qkv[(size_t)NPIX * QKVN];
__device__ __nv_bfloat16 g_xhi[(size_t)NPIX * DIM];
__device__ __nv_bfloat16 g_xlo[(size_t)NPIX * DIM];
__device__ __nv_bfloat16 g_w1hi[(size_t)QKVN * DIM];
__device__ __nv_bfloat16 g_w1lo[(size_t)QKVN * DIM];
__device__ __nv_bfloat16 g_ahi[(size_t)NPIX * DIM];
__device__ __nv_bfloat16 g_alo[(size_t)NPIX * DIM];
__device__ __nv_bfloat16 g_w2hi[(size_t)DIM * DIM];
__device__ __nv_bfloat16 g_w2lo[(size_t)DIM * DIM];

#define N_X  (NPIX * DIM)
#define N_W1 (QKVN * DIM)
#define N_W2 (DIM * DIM)

__device__ __forceinline__ uint32_t smem_u32(const void* p) {
    uint32_t a;
    asm("{ .reg .u64 t; cvta.to.shared.u64 t, %1; cvt.u32.u64 %0, t; }"
        : "=r"(a) : "l"(p));
    return a;
}
__device__ __forceinline__ void cp16(uint32_t dst, const void* src) {
    asm volatile("cp.async.cg.shared.global [%0], [%1], 16;"
                 :: "r"(dst), "l"(src));
}
__device__ __forceinline__ void cp_commit() {
    asm volatile("cp.async.commit_group;" ::: "memory");
}
__device__ __forceinline__ void cp_wait0() {
    asm volatile("cp.async.wait_group 0;" ::: "memory");
}

// ---------------------------------------------------------------------------
// fp32 -> bf16 hi/lo split for all three inputs in one launch.
// ---------------------------------------------------------------------------
__global__ void __launch_bounds__(256) cvt_all(
    const float* __restrict__ x, const float* __restrict__ w1,
    const float* __restrict__ w2,
    __nv_bfloat16* __restrict__ xhi, __nv_bfloat16* __restrict__ xlo,
    __nv_bfloat16* __restrict__ w1hi, __nv_bfloat16* __restrict__ w1lo,
    __nv_bfloat16* __restrict__ w2hi, __nv_bfloat16* __restrict__ w2lo)
{
    int i = (blockIdx.x * 256 + threadIdx.x) * 4;
    const float* src;
    __nv_bfloat16 *hi, *lo;
    if (i < N_X)              { src = x + i;             hi = xhi + i;  lo = xlo + i; }
    else if (i < N_X + N_W1)  { i -= N_X;  src = w1 + i; hi = w1hi + i; lo = w1lo + i; }
    else                      { i -= N_X + N_W1; src = w2 + i; hi = w2hi + i; lo = w2lo + i; }

    float4 v = *(const float4*)src;
    float f[4] = {v.x, v.y, v.z, v.w};
    __nv_bfloat16 h[4], l[4];
#pragma unroll
    for (int k = 0; k < 4; k++) {
        h[k] = __float2bfloat16(f[k]);
        l[k] = __float2bfloat16(f[k] - __bfloat162float(h[k]));
    }
    uint2 ph, pl;
    {
        __nv_bfloat162 t;
        t = __nv_bfloat162(h[0], h[1]); ph.x = *(uint32_t*)&t;
        t = __nv_bfloat162(h[2], h[3]); ph.y = *(uint32_t*)&t;
        t = __nv_bfloat162(l[0], l[1]); pl.x = *(uint32_t*)&t;
        t = __nv_bfloat162(l[2], l[3]); pl.y = *(uint32_t*)&t;
    }
    *(uint2*)hi = ph;
    *(uint2*)lo = pl;
}

// ---------------------------------------------------------------------------
// mma.sync bf16 GEMM (3xBF16 compensated): C[M,N] = A[M,K] @ B[N,K]^T + bias
// 128 x BN CTA tile, 256 threads = 8 warps in 2(m) x 4(n); warp 64 x (BN/4).
// ---------------------------------------------------------------------------
#define BK 32
#define ROWB 80
#define AMATB (128 * ROWB)

__device__ __forceinline__ void ldmx4(uint32_t* r, uint32_t addr) {
    asm volatile("ldmatrix.sync.aligned.m8n8.x4.shared.b16 {%0,%1,%2,%3}, [%4];"
                 : "=r"(r[0]), "=r"(r[1]), "=r"(r[2]), "=r"(r[3]) : "r"(addr));
}
__device__ __forceinline__ void ldmx2(uint32_t* r, uint32_t addr) {
    asm volatile("ldmatrix.sync.aligned.m8n8.x2.shared.b16 {%0,%1}, [%2];"
                 : "=r"(r[0]), "=r"(r[1]) : "r"(addr));
}
__device__ __forceinline__ void mma_bf16(float* c, const uint32_t* a, const uint32_t* b) {
    asm volatile(
        "mma.sync.aligned.m16n8k16.row.col.f32.bf16.bf16.f32 "
        "{%0,%1,%2,%3}, {%4,%5,%6,%7}, {%8,%9}, {%0,%1,%2,%3};"
        : "+f"(c[0]), "+f"(c[1]), "+f"(c[2]), "+f"(c[3])
        : "r"(a[0]), "r"(a[1]), "r"(a[2]), "r"(a[3]), "r"(b[0]), "r"(b[1]));
}

template<int BN>
__global__ void __launch_bounds__(256, 2) gemm_bf16x3(
    const __nv_bfloat16* __restrict__ Ahi, const __nv_bfloat16* __restrict__ Alo,
    const __nv_bfloat16* __restrict__ Bhi, const __nv_bfloat16* __restrict__ Blo,
    const float* __restrict__ bias, float* __restrict__ C,
    int M, int N, int K)
{
    constexpr int NI = BN / 32;
    constexpr int BMB = BN * ROWB;
    constexpr int STAGE = 2 * AMATB + 2 * BMB;
    constexpr int NT4 = (256 + 2 * BN) / 64;

    extern __shared__ char smem[];
    const uint32_t sb = smem_u32(smem);
    const int tid = threadIdx.x;
    const int wid = tid >> 5;
    const int lane = tid & 31;
    const int bm = blockIdx.y * 128;
    const int bn = blockIdx.x * BN;
    const int wm = (wid & 1) * 64;
    const int wn = (wid >> 1) * (BN / 4);

    const __nv_bfloat16* gAhi = Ahi + (size_t)bm * K;
    const __nv_bfloat16* gAlo = Alo + (size_t)bm * K;
    const __nv_bfloat16* gBhi = Bhi + (size_t)bn * K;
    const __nv_bfloat16* gBlo = Blo + (size_t)bn * K;

    float acc[4][NI][4];
#pragma unroll
    for (int mi = 0; mi < 4; mi++)
#pragma unroll
        for (int ni = 0; ni < NI; ni++)
#pragma unroll
            for (int e = 0; e < 4; e++) acc[mi][ni][e] = 0.f;

    const int nch = K / BK;

    auto load_stage = [&](int buf, int k0) {
        const uint32_t st = sb + buf * STAGE;
#pragma unroll
        for (int it = 0; it < NT4; it++) {
            const int f = tid + it * 256;
            const int r = f >> 2;
            const int c = f & 3;
            const __nv_bfloat16* src;
            uint32_t dst;
            if (r < 128)          { src = gAhi + (size_t)r * K;
                                    dst = st + r * ROWB; }
            else if (r < 256)     { src = gAlo + (size_t)(r - 128) * K;
                                    dst = st + AMATB + (r - 128) * ROWB; }
            else if (r < 256 + BN){ src = gBhi + (size_t)(r - 256) * K;
                                    dst = st + 2 * AMATB + (r - 256) * ROWB; }
            else                  { src = gBlo + (size_t)(r - 256 - BN) * K;
                                    dst = st + 2 * AMATB + BMB + (r - 256 - BN) * ROWB; }
            cp16(dst + c * 16, src + k0 + c * 8);
        }
    };

    const int a_r  = wm + (lane & 15);
    const int a_k  = (lane >> 4) * 8;
    const int b_nr = (lane & 7) + ((lane >> 4) & 1) * 8;
    const int b_k  = ((lane >> 3) & 1) * 8;

    load_stage(0, 0);
    cp_commit();

    for (int ch = 0; ch < nch; ch++) {
        cp_wait0();
        __syncthreads();
        if (ch + 1 < nch) {
            load_stage((ch + 1) & 1, (ch + 1) * BK);
            cp_commit();
        }

        const uint32_t st = sb + (ch & 1) * STAGE;
#pragma unroll
        for (int kk = 0; kk < 2; kk++) {
            uint32_t bh[NI][2], bl[NI][2];
            const uint32_t bb = st + 2 * AMATB + (uint32_t)((kk * 16 + b_k) * 2);
#pragma unroll
            for (int p = 0; p < NI / 2; p++) {
                uint32_t rh[4], rl[4];
                const uint32_t addr = bb + (wn + p * 16 + b_nr) * ROWB;
                ldmx4(rh, addr);
                ldmx4(rl, addr + BMB);
                bh[2 * p][0] = rh[0]; bh[2 * p][1] = rh[1];
                bh[2 * p + 1][0] = rh[2]; bh[2 * p + 1][1] = rh[3];
                bl[2 * p][0] = rl[0]; bl[2 * p][1] = rl[1];
                bl[2 * p + 1][0] = rl[2]; bl[2 * p + 1][1] = rl[3];
            }
            if (NI & 1) {
                const uint32_t addr = st + 2 * AMATB
                    + (uint32_t)((wn + (NI - 1) * 8 + (lane & 7)) * ROWB
                                 + (kk * 16 + b_k) * 2);
                ldmx2(bh[NI - 1], addr);
                ldmx2(bl[NI - 1], addr + BMB);
            }
            const uint32_t ab = st + (uint32_t)(a_r * ROWB + (kk * 16 + a_k) * 2);
#pragma unroll
            for (int mi = 0; mi < 4; mi++) {
                uint32_t ah[4], al[4];
                ldmx4(ah, ab + mi * 16 * ROWB);
                ldmx4(al, ab + AMATB + mi * 16 * ROWB);
#pragma unroll
                for (int ni = 0; ni < NI; ni++) {
                    mma_bf16(acc[mi][ni], ah, bh[ni]);
                    mma_bf16(acc[mi][ni], ah, bl[ni]);
                    mma_bf16(acc[mi][ni], al, bh[ni]);
                }
            }
        }
    }

    const int g = lane >> 2;
    const int tg = lane & 3;
#pragma unroll
    for (int mi = 0; mi < 4; mi++) {
        const int r0 = bm + wm + mi * 16 + g;
#pragma unroll
        for (int ni = 0; ni < NI; ni++) {
            const int col = bn + wn + ni * 8 + tg * 2;
            const float2 bv = *(const float2*)(bias + col);
            float2 o0, o1;
            o0.x = acc[mi][ni][0] + bv.x; o0.y = acc[mi][ni][1] + bv.y;
            o1.x = acc[mi][ni][2] + bv.x; o1.y = acc[mi][ni][3] + bv.y;
            *(float2*)(C + (size_t)r0 * N + col) = o0;
            *(float2*)(C + (size_t)(r0 + 8) * N + col) = o1;
        }
    }
}

#define GEMM_SMEM_96  (2 * (2 * AMATB + 2 * 96 * ROWB))
#define GEMM_SMEM_128 (2 * (2 * AMATB + 2 * 128 * ROWB))

// ---------------------------------------------------------------------------
// Neighborhood attention, smem-tiled, R7 compute structure.
// Block = 8 adjacent pixels x 1 head. k/v window (7 x wb <= 7x14 neighbors,
// [nbr][64] layout) cp.async'd into smem once, then:
//   scores: half-warp per neighbor, float4 smem reads, 4 shfls / 2 neighbors
//   AV: float2 smem reads, probs broadcast from smem
// ---------------------------------------------------------------------------
#define A_OK 0                     // k: 98 x 64 floats
#define A_OV (98 * 64)             // v: 98 x 64 floats
#define A_OP (2 * 98 * 64)         // probs: 8 x 52
#define ATTN_SMEM ((A_OP + 8 * 52) * 4)   // 51840 B

__global__ void __launch_bounds__(256) nat_attn(
    const float* __restrict__ qkv, const float* __restrict__ rpb,
    __nv_bfloat16* __restrict__ ahi, __nv_bfloat16* __restrict__ alo)
{
    extern __shared__ float sm[];
    const uint32_t sb = smem_u32(sm);

    const int tid = threadIdx.x;
    const int warp = tid >> 5;
    const int lane = tid & 31;
    const int jb = blockIdx.x * 8;
    const int i = blockIdx.y;
    const int h = blockIdx.z;
    const int j = jb + warp;
    const int pix = i * HWDIM + j;

    const int sh = min(max(i - 3, 0), HWDIM - KWIN);
    const int sw = min(max(j - 3, 0), HWDIM - KWIN);
    const int cmin = min(max(jb - 3, 0), HWDIM - KWIN);
    const int cmax = min(max(jb + 4, 0), HWDIM - KWIN) + 6;
    const int wb = cmax - cmin + 1;            // 11..14
    const int swloc = sw - cmin;

    // --- cooperative k/v load: nseg = 7*wb segments of 64 floats each ---
    {
        const int nseg = 7 * wb;
        const int part = tid & 15;             // float4 index within segment
        for (int s = tid >> 4; s < nseg; s += 16) {
            const int a = s / wb;
            const int c = s - a * wb;
            const float* kg = qkv + (size_t)((sh + a) * HWDIM + cmin + c) * QKVN
                            + DIM + h * HD;
            const uint32_t nb = (uint32_t)(a * 14 + c) * 64 + part * 4;
            cp16(sb + (A_OK + nb) * 4, kg + part * 4);
            cp16(sb + (A_OV + nb) * 4, kg + DIM + part * 4);
        }
        cp_commit();
    }

    // q while loads are in flight
    const int half = lane >> 4;
    const int l15 = lane & 15;
    float4 q4 = ((const float4*)(qkv + (size_t)pix * QKVN + h * HD))[l15];
    q4.x *= 0.125f; q4.y *= 0.125f; q4.z *= 0.125f; q4.w *= 0.125f;

    const float* rp = rpb + h * 169 + (sh - i + 6) * 13 + (sw - j + 6);

    cp_wait0();
    __syncthreads();

    // --- scores: 2 neighbors per iteration (one per half-warp) ---
    float* sprob = &sm[A_OP + warp * 52];
    const float* sk = &sm[A_OK + swloc * 64];
#pragma unroll
    for (int it = 0; it < 25; it++) {
        const int t = 2 * it + half;
        const bool valid = (t < 49);
        const int tt = valid ? t : 0;
        const unsigned a = ((unsigned)tt * 37u) >> 8;    // tt / 7
        const int c = tt - 7 * (int)a;
        const float4 kv = *(const float4*)&sk[((int)a * 14 + c) * 64 + l15 * 4];
        float s = q4.x * kv.x + q4.y * kv.y + q4.z * kv.z + q4.w * kv.w;
        s += __shfl_xor_sync(0xffffffffu, s, 1);
        s += __shfl_xor_sync(0xffffffffu, s, 2);
        s += __shfl_xor_sync(0xffffffffu, s, 4);
        s += __shfl_xor_sync(0xffffffffu, s, 8);
        if (l15 == 0 && valid)
            sprob[t] = s + rp[a * 13 + c];
    }
    __syncwarp();

    // --- softmax over 49 scores ---
    float s0 = sprob[lane];
    float s1 = (lane + 32 < 49) ? sprob[lane + 32] : -1e30f;
    float m = fmaxf(s0, s1);
#pragma unroll
    for (int o = 16; o; o >>= 1)
        m = fmaxf(m, __shfl_xor_sync(0xffffffffu, m, o));
    float e0 = __expf(s0 - m);
    float e1 = (lane + 32 < 49) ? __expf(s1 - m) : 0.f;
    float sum = e0 + e1;
#pragma unroll
    for (int o = 16; o; o >>= 1)
        sum += __shfl_xor_sync(0xffffffffu, sum, o);
    const float inv = __fdividef(1.f, sum);
    sprob[lane] = e0 * inv;
    if (lane + 32 < 49) sprob[lane + 32] = e1 * inv;
    __syncwarp();

    // --- AV: lane owns dims 2*lane, 2*lane+1 ---
    float ax = 0.f, ay = 0.f;
    const float* sv = &sm[A_OV + swloc * 64 + 2 * lane];
#pragma unroll
    for (int a = 0; a < KWIN; a++) {
#pragma unroll
        for (int c = 0; c < KWIN; c++) {
            const float at = sprob[a * 7 + c];
            const float2 vv = *(const float2*)&sv[(a * 14 + c) * 64];
            ax = fmaf(at, vv.x, ax);
            ay = fmaf(at, vv.y, ay);
        }
    }

    // --- fused bf16 hi/lo epilogue ---
    __nv_bfloat16 hx = __float2bfloat16(ax);
    __nv_bfloat16 hy = __float2bfloat16(ay);
    __nv_bfloat16 lx = __float2bfloat16(ax - __bfloat162float(hx));
    __nv_bfloat16 ly = __float2bfloat16(ay - __bfloat162float(hy));
    const size_t oidx = (size_t)pix * DIM + h * HD + 2 * lane;
    __nv_bfloat162 ph(hx, hy), pl(lx, ly);
    *(__nv_bfloat162*)(ahi + oidx) = ph;
    *(__nv_bfloat162*)(alo + oidx) = pl;
}

// ---------------------------------------------------------------------------
extern "C" void kernel_launch(void* const* d_in, const int* in_sizes, int n_in,
                              void* d_out, int out_size)
{
    const float* x      = (const float*)d_in[0];
    const float* qkv_w  = (const float*)d_in[1];
    const float* qkv_b  = (const float*)d_in[2];
    const float* rpb    = (const float*)d_in[3];
    const float* proj_w = (const float*)d_in[4];
    const float* proj_b = (const float*)d_in[5];
    float* out = (float*)d_out;

    float *qkv;
    __nv_bfloat16 *xhi, *xlo, *w1hi, *w1lo, *ahi, *alo, *w2hi, *w2lo;
    cudaGetSymbolAddress((void**)&qkv, g_qkv);
    cudaGetSymbolAddress((void**)&xhi, g_xhi);
    cudaGetSymbolAddress((void**)&xlo, g_xlo);
    cudaGetSymbolAddress((void**)&w1hi, g_w1hi);
    cudaGetSymbolAddress((void**)&w1lo, g_w1lo);
    cudaGetSymbolAddress((void**)&ahi, g_ahi);
    cudaGetSymbolAddress((void**)&alo, g_alo);
    cudaGetSymbolAddress((void**)&w2hi, g_w2hi);
    cudaGetSymbolAddress((void**)&w2lo, g_w2lo);

    cudaFuncSetAttribute(gemm_bf16x3<96>,
                         cudaFuncAttributeMaxDynamicSharedMemorySize, GEMM_SMEM_96);
    cudaFuncSetAttribute(gemm_bf16x3<128>,
                         cudaFuncAttributeMaxDynamicSharedMemorySize, GEMM_SMEM_128);
    cudaFuncSetAttribute(nat_attn,
                         cudaFuncAttributeMaxDynamicSharedMemorySize, ATTN_SMEM);

    // 0) Split all fp32 inputs into bf16 hi/lo (one launch)
    cvt_all<<<(N_X + N_W1 + N_W2) / 1024, 256>>>(
        x, qkv_w, proj_w, xhi, xlo, w1hi, w1lo, w2hi, w2lo);

    // 1) QKV projection: 128x96 tiles (800 CTAs)
    gemm_bf16x3<96><<<dim3(QKVN / 96, NPIX / 128), 256, GEMM_SMEM_96>>>(
        xhi, xlo, w1hi, w1lo, qkv_b, qkv, NPIX, QKVN, DIM);

    // 2) Neighborhood attention (smem-tiled; emits bf16 hi/lo directly)
    nat_attn<<<dim3(HWDIM / 8, HWDIM, NHEAD), 256, ATTN_SMEM>>>(
        qkv, rpb, ahi, alo);

    // 3) Output projection: 128x128 tiles (200 CTAs, single wave)
    gemm_bf16x3<128><<<dim3(DIM / 128, NPIX / 128), 256, GEMM_SMEM_128>>>(
        ahi, alo, w2hi, w2lo, proj_b, out, NPIX, DIM, DIM);
}

// round 10
// speedup vs baseline: 1.0271x; 1.0271x over previous
#include <cuda_runtime.h>
#include <cuda_bf16.h>
#include <cstdint>
#include <math.h>

// Problem constants
#define HWDIM 80
#define NPIX  6400
#define DIM   512
#define QKVN  1536
#define NHEAD 8
#define HD    64
#define KWIN  7

// Scratch (allocation-free rule: __device__ globals)
__device__ float g_qkv[(size_t)NPIX * QKVN];
__device__ __nv_bfloat16 g_xhi[(size_t)NPIX * DIM];
__device__ __nv_bfloat16 g_xlo[(size_t)NPIX * DIM];
__device__ __nv_bfloat16 g_w1hi[(size_t)QKVN * DIM];
__device__ __nv_bfloat16 g_w1lo[(size_t)QKVN * DIM];
__device__ __nv_bfloat16 g_ahi[(size_t)NPIX * DIM];
__device__ __nv_bfloat16 g_alo[(size_t)NPIX * DIM];
__device__ __nv_bfloat16 g_w2hi[(size_t)DIM * DIM];
__device__ __nv_bfloat16 g_w2lo[(size_t)DIM * DIM];

#define N_X  (NPIX * DIM)
#define N_W1 (QKVN * DIM)
#define N_W2 (DIM * DIM)

__device__ __forceinline__ uint32_t smem_u32(const void* p) {
    uint32_t a;
    asm("{ .reg .u64 t; cvta.to.shared.u64 t, %1; cvt.u32.u64 %0, t; }"
        : "=r"(a) : "l"(p));
    return a;
}
__device__ __forceinline__ void cp16(uint32_t dst, const void* src) {
    asm volatile("cp.async.cg.shared.global [%0], [%1], 16;"
                 :: "r"(dst), "l"(src));
}
__device__ __forceinline__ void cp_commit() {
    asm volatile("cp.async.commit_group;" ::: "memory");
}
__device__ __forceinline__ void cp_wait0() {
    asm volatile("cp.async.wait_group 0;" ::: "memory");
}

// ---------------------------------------------------------------------------
// Zero-init for the split-K accumulation target.
// ---------------------------------------------------------------------------
__global__ void __launch_bounds__(256) zero_out(float* __restrict__ p)
{
    const int i = (blockIdx.x * 256 + threadIdx.x) * 4;
    float4 z; z.x = 0.f; z.y = 0.f; z.z = 0.f; z.w = 0.f;
    *(float4*)(p + i) = z;
}

// ---------------------------------------------------------------------------
// fp32 -> bf16 hi/lo split for all three inputs in one launch.
// ---------------------------------------------------------------------------
__global__ void __launch_bounds__(256) cvt_all(
    const float* __restrict__ x, const float* __restrict__ w1,
    const float* __restrict__ w2,
    __nv_bfloat16* __restrict__ xhi, __nv_bfloat16* __restrict__ xlo,
    __nv_bfloat16* __restrict__ w1hi, __nv_bfloat16* __restrict__ w1lo,
    __nv_bfloat16* __restrict__ w2hi, __nv_bfloat16* __restrict__ w2lo)
{
    int i = (blockIdx.x * 256 + threadIdx.x) * 4;
    const float* src;
    __nv_bfloat16 *hi, *lo;
    if (i < N_X)              { src = x + i;             hi = xhi + i;  lo = xlo + i; }
    else if (i < N_X + N_W1)  { i -= N_X;  src = w1 + i; hi = w1hi + i; lo = w1lo + i; }
    else                      { i -= N_X + N_W1; src = w2 + i; hi = w2hi + i; lo = w2lo + i; }

    float4 v = *(const float4*)src;
    float f[4] = {v.x, v.y, v.z, v.w};
    __nv_bfloat16 h[4], l[4];
#pragma unroll
    for (int k = 0; k < 4; k++) {
        h[k] = __float2bfloat16(f[k]);
        l[k] = __float2bfloat16(f[k] - __bfloat162float(h[k]));
    }
    uint2 ph, pl;
    {
        __nv_bfloat162 t;
        t = __nv_bfloat162(h[0], h[1]); ph.x = *(uint32_t*)&t;
        t = __nv_bfloat162(h[2], h[3]); ph.y = *(uint32_t*)&t;
        t = __nv_bfloat162(l[0], l[1]); pl.x = *(uint32_t*)&t;
        t = __nv_bfloat162(l[2], l[3]); pl.y = *(uint32_t*)&t;
    }
    *(uint2*)hi = ph;
    *(uint2*)lo = pl;
}

// ---------------------------------------------------------------------------
// mma.sync bf16 GEMM (3xBF16 compensated): C[M,N] = A[M,K] @ B[N,K]^T + bias
// 128 x BN CTA tile, 256 threads = 8 warps in 2(m) x 4(n); warp 64 x (BN/4).
// SK-way split-K: blockIdx.z selects K-slice; SK>1 accumulates via atomicAdd
// into a zero-initialized C (bias contributed by slice 0 only).
// ---------------------------------------------------------------------------
#define BK 32
#define ROWB 80
#define AMATB (128 * ROWB)

__device__ __forceinline__ void ldmx4(uint32_t* r, uint32_t addr) {
    asm volatile("ldmatrix.sync.aligned.m8n8.x4.shared.b16 {%0,%1,%2,%3}, [%4];"
                 : "=r"(r[0]), "=r"(r[1]), "=r"(r[2]), "=r"(r[3]) : "r"(addr));
}
__device__ __forceinline__ void ldmx2(uint32_t* r, uint32_t addr) {
    asm volatile("ldmatrix.sync.aligned.m8n8.x2.shared.b16 {%0,%1}, [%2];"
                 : "=r"(r[0]), "=r"(r[1]) : "r"(addr));
}
__device__ __forceinline__ void mma_bf16(float* c, const uint32_t* a, const uint32_t* b) {
    asm volatile(
        "mma.sync.aligned.m16n8k16.row.col.f32.bf16.bf16.f32 "
        "{%0,%1,%2,%3}, {%4,%5,%6,%7}, {%8,%9}, {%0,%1,%2,%3};"
        : "+f"(c[0]), "+f"(c[1]), "+f"(c[2]), "+f"(c[3])
        : "r"(a[0]), "r"(a[1]), "r"(a[2]), "r"(a[3]), "r"(b[0]), "r"(b[1]));
}

template<int BN, int SK>
__global__ void __launch_bounds__(256, 2) gemm_bf16x3(
    const __nv_bfloat16* __restrict__ Ahi, const __nv_bfloat16* __restrict__ Alo,
    const __nv_bfloat16* __restrict__ Bhi, const __nv_bfloat16* __restrict__ Blo,
    const float* __restrict__ bias, float* __restrict__ C,
    int M, int N, int K)
{
    constexpr int NI = BN / 32;
    constexpr int BMB = BN * ROWB;
    constexpr int STAGE = 2 * AMATB + 2 * BMB;
    constexpr int NT4 = (256 + 2 * BN) / 64;

    extern __shared__ char smem[];
    const uint32_t sb = smem_u32(smem);
    const int tid = threadIdx.x;
    const int wid = tid >> 5;
    const int lane = tid & 31;
    const int bm = blockIdx.y * 128;
    const int bn = blockIdx.x * BN;
    const int wm = (wid & 1) * 64;
    const int wn = (wid >> 1) * (BN / 4);
    const int kslice = (SK > 1) ? blockIdx.z : 0;
    const int Keff = K / SK;
    const int kbase = kslice * Keff;

    const __nv_bfloat16* gAhi = Ahi + (size_t)bm * K + kbase;
    const __nv_bfloat16* gAlo = Alo + (size_t)bm * K + kbase;
    const __nv_bfloat16* gBhi = Bhi + (size_t)bn * K + kbase;
    const __nv_bfloat16* gBlo = Blo + (size_t)bn * K + kbase;

    float acc[4][NI][4];
#pragma unroll
    for (int mi = 0; mi < 4; mi++)
#pragma unroll
        for (int ni = 0; ni < NI; ni++)
#pragma unroll
            for (int e = 0; e < 4; e++) acc[mi][ni][e] = 0.f;

    const int nch = Keff / BK;

    auto load_stage = [&](int buf, int k0) {
        const uint32_t st = sb + buf * STAGE;
#pragma unroll
        for (int it = 0; it < NT4; it++) {
            const int f = tid + it * 256;
            const int r = f >> 2;
            const int c = f & 3;
            const __nv_bfloat16* src;
            uint32_t dst;
            if (r < 128)          { src = gAhi + (size_t)r * K;
                                    dst = st + r * ROWB; }
            else if (r < 256)     { src = gAlo + (size_t)(r - 128) * K;
                                    dst = st + AMATB + (r - 128) * ROWB; }
            else if (r < 256 + BN){ src = gBhi + (size_t)(r - 256) * K;
                                    dst = st + 2 * AMATB + (r - 256) * ROWB; }
            else                  { src = gBlo + (size_t)(r - 256 - BN) * K;
                                    dst = st + 2 * AMATB + BMB + (r - 256 - BN) * ROWB; }
            cp16(dst + c * 16, src + k0 + c * 8);
        }
    };

    const int a_r  = wm + (lane & 15);
    const int a_k  = (lane >> 4) * 8;
    const int b_nr = (lane & 7) + ((lane >> 4) & 1) * 8;
    const int b_k  = ((lane >> 3) & 1) * 8;

    load_stage(0, 0);
    cp_commit();

    for (int ch = 0; ch < nch; ch++) {
        cp_wait0();
        __syncthreads();
        if (ch + 1 < nch) {
            load_stage((ch + 1) & 1, (ch + 1) * BK);
            cp_commit();
        }

        const uint32_t st = sb + (ch & 1) * STAGE;
#pragma unroll
        for (int kk = 0; kk < 2; kk++) {
            uint32_t bh[NI][2], bl[NI][2];
            const uint32_t bb = st + 2 * AMATB + (uint32_t)((kk * 16 + b_k) * 2);
#pragma unroll
            for (int p = 0; p < NI / 2; p++) {
                uint32_t rh[4], rl[4];
                const uint32_t addr = bb + (wn + p * 16 + b_nr) * ROWB;
                ldmx4(rh, addr);
                ldmx4(rl, addr + BMB);
                bh[2 * p][0] = rh[0]; bh[2 * p][1] = rh[1];
                bh[2 * p + 1][0] = rh[2]; bh[2 * p + 1][1] = rh[3];
                bl[2 * p][0] = rl[0]; bl[2 * p][1] = rl[1];
                bl[2 * p + 1][0] = rl[2]; bl[2 * p + 1][1] = rl[3];
            }
            if (NI & 1) {
                const uint32_t addr = st + 2 * AMATB
                    + (uint32_t)((wn + (NI - 1) * 8 + (lane & 7)) * ROWB
                                 + (kk * 16 + b_k) * 2);
                ldmx2(bh[NI - 1], addr);
                ldmx2(bl[NI - 1], addr + BMB);
            }
            const uint32_t ab = st + (uint32_t)(a_r * ROWB + (kk * 16 + a_k) * 2);
#pragma unroll
            for (int mi = 0; mi < 4; mi++) {
                uint32_t ah[4], al[4];
                ldmx4(ah, ab + mi * 16 * ROWB);
                ldmx4(al, ab + AMATB + mi * 16 * ROWB);
#pragma unroll
                for (int ni = 0; ni < NI; ni++) {
                    mma_bf16(acc[mi][ni], ah, bh[ni]);
                    mma_bf16(acc[mi][ni], ah, bl[ni]);
                    mma_bf16(acc[mi][ni], al, bh[ni]);
                }
            }
        }
    }

    const int g = lane >> 2;
    const int tg = lane & 3;
#pragma unroll
    for (int mi = 0; mi < 4; mi++) {
        const int r0 = bm + wm + mi * 16 + g;
#pragma unroll
        for (int ni = 0; ni < NI; ni++) {
            const int col = bn + wn + ni * 8 + tg * 2;
            const float2 bv = *(const float2*)(bias + col);
            if (SK == 1) {
                float2 o0, o1;
                o0.x = acc[mi][ni][0] + bv.x; o0.y = acc[mi][ni][1] + bv.y;
                o1.x = acc[mi][ni][2] + bv.x; o1.y = acc[mi][ni][3] + bv.y;
                *(float2*)(C + (size_t)r0 * N + col) = o0;
                *(float2*)(C + (size_t)(r0 + 8) * N + col) = o1;
            } else {
                const float bx = (kslice == 0) ? bv.x : 0.f;
                const float by = (kslice == 0) ? bv.y : 0.f;
                float* p0 = C + (size_t)r0 * N + col;
                float* p1 = C + (size_t)(r0 + 8) * N + col;
                atomicAdd(p0,     acc[mi][ni][0] + bx);
                atomicAdd(p0 + 1, acc[mi][ni][1] + by);
                atomicAdd(p1,     acc[mi][ni][2] + bx);
                atomicAdd(p1 + 1, acc[mi][ni][3] + by);
            }
        }
    }
}

#define GEMM_SMEM_96  (2 * (2 * AMATB + 2 * 96 * ROWB))
#define GEMM_SMEM_128 (2 * (2 * AMATB + 2 * 128 * ROWB))

// ---------------------------------------------------------------------------
// Neighborhood attention: one warp per (pixel, head) [R7 structure, gmem/L1].
// Score phase: half-warp per neighbor, float4 loads, 4 shfl per 2 neighbors.
// Probs parked in smem; AV reads via LDS broadcast. bf16 hi/lo epilogue.
// ---------------------------------------------------------------------------
__global__ void __launch_bounds__(256) nat_attn(
    const float* __restrict__ qkv, const float* __restrict__ rpb,
    __nv_bfloat16* __restrict__ ahi, __nv_bfloat16* __restrict__ alo)
{
    __shared__ float sprob[8][52];

    const int warp = threadIdx.x >> 5;
    const int lane = threadIdx.x & 31;
    const int j = blockIdx.x * 8 + warp;
    const int i = blockIdx.y;
    const int h = blockIdx.z;
    const int pix = i * HWDIM + j;

    const int sh = min(max(i - 3, 0), HWDIM - KWIN);
    const int sw = min(max(j - 3, 0), HWDIM - KWIN);

    const int half = lane >> 4;
    const int l15 = lane & 15;

    float4 q4 = ((const float4*)(qkv + (size_t)pix * QKVN + h * HD))[l15];
    q4.x *= 0.125f; q4.y *= 0.125f; q4.z *= 0.125f; q4.w *= 0.125f;

    const float* rp = rpb + h * 169 + (sh - i + 6) * 13 + (sw - j + 6);
    const float* kb = qkv + (size_t)(sh * HWDIM + sw) * QKVN + DIM + h * HD;

#pragma unroll
    for (int it = 0; it < 25; it++) {
        const int t = 2 * it + half;
        const bool valid = (t < 49);
        const int tt = valid ? t : 0;
        const unsigned a = ((unsigned)tt * 37u) >> 8;
        const int c = tt - 7 * (int)a;
        const float4 kv = ((const float4*)(kb + ((size_t)a * HWDIM + c) * QKVN))[l15];
        float s = q4.x * kv.x + q4.y * kv.y + q4.z * kv.z + q4.w * kv.w;
        s += __shfl_xor_sync(0xffffffffu, s, 1);
        s += __shfl_xor_sync(0xffffffffu, s, 2);
        s += __shfl_xor_sync(0xffffffffu, s, 4);
        s += __shfl_xor_sync(0xffffffffu, s, 8);
        if (l15 == 0 && valid)
            sprob[warp][t] = s + rp[a * 13 + c];
    }
    __syncwarp();

    float s0 = sprob[warp][lane];
    float s1 = (lane + 32 < 49) ? sprob[warp][lane + 32] : -1e30f;
    float m = fmaxf(s0, s1);
#pragma unroll
    for (int o = 16; o; o >>= 1)
        m = fmaxf(m, __shfl_xor_sync(0xffffffffu, m, o));
    float e0 = __expf(s0 - m);
    float e1 = (lane + 32 < 49) ? __expf(s1 - m) : 0.f;
    float sum = e0 + e1;
#pragma unroll
    for (int o = 16; o; o >>= 1)
        sum += __shfl_xor_sync(0xffffffffu, sum, o);
    const float inv = __fdividef(1.f, sum);
    sprob[warp][lane] = e0 * inv;
    if (lane + 32 < 49) sprob[warp][lane + 32] = e1 * inv;
    __syncwarp();

    float ax = 0.f, ay = 0.f;
    const float* vb = qkv + (size_t)(sh * HWDIM + sw) * QKVN + 2 * DIM + h * HD;
#pragma unroll
    for (int a = 0; a < KWIN; a++) {
#pragma unroll
        for (int c = 0; c < KWIN; c++) {
            const float at = sprob[warp][a * 7 + c];
            const float2 vv = ((const float2*)(vb + ((size_t)a * HWDIM + c) * QKVN))[lane];
            ax = fmaf(at, vv.x, ax);
            ay = fmaf(at, vv.y, ay);
        }
    }

    __nv_bfloat16 hx = __float2bfloat16(ax);
    __nv_bfloat16 hy = __float2bfloat16(ay);
    __nv_bfloat16 lx = __float2bfloat16(ax - __bfloat162float(hx));
    __nv_bfloat16 ly = __float2bfloat16(ay - __bfloat162float(hy));
    const size_t oidx = (size_t)pix * DIM + h * HD + 2 * lane;
    __nv_bfloat162 ph(hx, hy), pl(lx, ly);
    *(__nv_bfloat162*)(ahi + oidx) = ph;
    *(__nv_bfloat162*)(alo + oidx) = pl;
}

// ---------------------------------------------------------------------------
extern "C" void kernel_launch(void* const* d_in, const int* in_sizes, int n_in,
                              void* d_out, int out_size)
{
    const float* x      = (const float*)d_in[0];
    const float* qkv_w  = (const float*)d_in[1];
    const float* qkv_b  = (const float*)d_in[2];
    const float* rpb    = (const float*)d_in[3];
    const float* proj_w = (const float*)d_in[4];
    const float* proj_b = (const float*)d_in[5];
    float* out = (float*)d_out;

    float *qkv;
    __nv_bfloat16 *xhi, *xlo, *w1hi, *w1lo, *ahi, *alo, *w2hi, *w2lo;
    cudaGetSymbolAddress((void**)&qkv, g_qkv);
    cudaGetSymbolAddress((void**)&xhi, g_xhi);
    cudaGetSymbolAddress((void**)&xlo, g_xlo);
    cudaGetSymbolAddress((void**)&w1hi, g_w1hi);
    cudaGetSymbolAddress((void**)&w1lo, g_w1lo);
    cudaGetSymbolAddress((void**)&ahi, g_ahi);
    cudaGetSymbolAddress((void**)&alo, g_alo);
    cudaGetSymbolAddress((void**)&w2hi, g_w2hi);
    cudaGetSymbolAddress((void**)&w2lo, g_w2lo);

    cudaFuncSetAttribute((const void*)gemm_bf16x3<96, 1>,
                         cudaFuncAttributeMaxDynamicSharedMemorySize, GEMM_SMEM_96);
    cudaFuncSetAttribute((const void*)gemm_bf16x3<128, 2>,
                         cudaFuncAttributeMaxDynamicSharedMemorySize, GEMM_SMEM_128);

    // 0) Zero the split-K target + split fp32 inputs into bf16 hi/lo
    zero_out<<<NPIX * DIM / 1024, 256>>>(out);
    cvt_all<<<(N_X + N_W1 + N_W2) / 1024, 256>>>(
        x, qkv_w, proj_w, xhi, xlo, w1hi, w1lo, w2hi, w2lo);

    // 1) QKV projection: 128x96 tiles (800 CTAs)
    gemm_bf16x3<96, 1><<<dim3(QKVN / 96, NPIX / 128), 256, GEMM_SMEM_96>>>(
        xhi, xlo, w1hi, w1lo, qkv_b, qkv, NPIX, QKVN, DIM);

    // 2) Neighborhood attention (emits bf16 hi/lo directly)
    nat_attn<<<dim3(HWDIM / 8, HWDIM, NHEAD), 256>>>(qkv, rpb, ahi, alo);

    // 3) Output projection: 128x128 tiles, split-K=2 (400 CTAs)
    gemm_bf16x3<128, 2><<<dim3(DIM / 128, NPIX / 128, 2), 256, GEMM_SMEM_128>>>(
        ahi, alo, w2hi, w2lo, proj_b, out, NPIX, DIM, DIM);
}

// round 12
// speedup vs baseline: 1.1077x; 1.0785x over previous
#include <cuda_runtime.h>
#include <cuda_bf16.h>
#include <cuda_fp16.h>
#include <cstdint>
#include <math.h>

// Problem constants
#define HWDIM 80
#define NPIX  6400
#define DIM   512
#define QKVN  1536
#define NHEAD 8
#define HD    64
#define KWIN  7

// Scratch (allocation-free rule: __device__ globals)
__device__ float g_q[(size_t)NPIX * DIM];            // q fp32
__device__ __half g_kvh[(size_t)NPIX * 1024];        // k|v fp16
__device__ __nv_bfloat16 g_xhi[(size_t)NPIX * DIM];
__device__ __nv_bfloat16 g_xlo[(size_t)NPIX * DIM];
__device__ __nv_bfloat16 g_w1hi[(size_t)QKVN * DIM];
__device__ __nv_bfloat16 g_w1lo[(size_t)QKVN * DIM];
__device__ __nv_bfloat16 g_ahi[(size_t)NPIX * DIM];
__device__ __nv_bfloat16 g_alo[(size_t)NPIX * DIM];
__device__ __nv_bfloat16 g_w2hi[(size_t)DIM * DIM];
__device__ __nv_bfloat16 g_w2lo[(size_t)DIM * DIM];

#define N_X  (NPIX * DIM)
#define N_W1 (QKVN * DIM)
#define N_W2 (DIM * DIM)

__device__ __forceinline__ uint32_t smem_u32(const void* p) {
    uint32_t a;
    asm("{ .reg .u64 t; cvta.to.shared.u64 t, %1; cvt.u32.u64 %0, t; }"
        : "=r"(a) : "l"(p));
    return a;
}
__device__ __forceinline__ void cp16(uint32_t dst, const void* src) {
    asm volatile("cp.async.cg.shared.global [%0], [%1], 16;"
                 :: "r"(dst), "l"(src));
}
__device__ __forceinline__ void cp_commit() {
    asm volatile("cp.async.commit_group;" ::: "memory");
}
__device__ __forceinline__ void cp_wait0() {
    asm volatile("cp.async.wait_group 0;" ::: "memory");
}

// ---------------------------------------------------------------------------
// Zero-init for the split-K accumulation target.
// ---------------------------------------------------------------------------
__global__ void __launch_bounds__(256) zero_out(float* __restrict__ p)
{
    const int i = (blockIdx.x * 256 + threadIdx.x) * 4;
    float4 z; z.x = 0.f; z.y = 0.f; z.z = 0.f; z.w = 0.f;
    *(float4*)(p + i) = z;
}

// ---------------------------------------------------------------------------
// fp32 -> bf16 hi/lo split for all three inputs in one launch.
// ---------------------------------------------------------------------------
__global__ void __launch_bounds__(256) cvt_all(
    const float* __restrict__ x, const float* __restrict__ w1,
    const float* __restrict__ w2,
    __nv_bfloat16* __restrict__ xhi, __nv_bfloat16* __restrict__ xlo,
    __nv_bfloat16* __restrict__ w1hi, __nv_bfloat16* __restrict__ w1lo,
    __nv_bfloat16* __restrict__ w2hi, __nv_bfloat16* __restrict__ w2lo)
{
    int i = (blockIdx.x * 256 + threadIdx.x) * 4;
    const float* src;
    __nv_bfloat16 *hi, *lo;
    if (i < N_X)              { src = x + i;             hi = xhi + i;  lo = xlo + i; }
    else if (i < N_X + N_W1)  { i -= N_X;  src = w1 + i; hi = w1hi + i; lo = w1lo + i; }
    else                      { i -= N_X + N_W1; src = w2 + i; hi = w2hi + i; lo = w2lo + i; }

    float4 v = *(const float4*)src;
    float f[4] = {v.x, v.y, v.z, v.w};
    __nv_bfloat16 h[4], l[4];
#pragma unroll
    for (int k = 0; k < 4; k++) {
        h[k] = __float2bfloat16(f[k]);
        l[k] = __float2bfloat16(f[k] - __bfloat162float(h[k]));
    }
    uint2 ph, pl;
    {
        __nv_bfloat162 t;
        t = __nv_bfloat162(h[0], h[1]); ph.x = *(uint32_t*)&t;
        t = __nv_bfloat162(h[2], h[3]); ph.y = *(uint32_t*)&t;
        t = __nv_bfloat162(l[0], l[1]); pl.x = *(uint32_t*)&t;
        t = __nv_bfloat162(l[2], l[3]); pl.y = *(uint32_t*)&t;
    }
    *(uint2*)hi = ph;
    *(uint2*)lo = pl;
}

// ---------------------------------------------------------------------------
// mma.sync bf16 GEMM (3xBF16 compensated): C = A @ B^T + bias
// 128 x BN CTA tile, 256 threads = 8 warps in 2(m) x 4(n); warp 64 x (BN/4).
// EPI=0: fp32 C (SK-way split-K via atomics when SK>1).
// EPI=1: QKV split epilogue — cols [0,512) fp32 -> C (stride 512),
//                             cols [512,1536) fp16 -> C2 (stride 1024).
// ---------------------------------------------------------------------------
#define BK 32
#define ROWB 80
#define AMATB (128 * ROWB)

__device__ __forceinline__ void ldmx4(uint32_t* r, uint32_t addr) {
    asm volatile("ldmatrix.sync.aligned.m8n8.x4.shared.b16 {%0,%1,%2,%3}, [%4];"
                 : "=r"(r[0]), "=r"(r[1]), "=r"(r[2]), "=r"(r[3]) : "r"(addr));
}
__device__ __forceinline__ void ldmx2(uint32_t* r, uint32_t addr) {
    asm volatile("ldmatrix.sync.aligned.m8n8.x2.shared.b16 {%0,%1}, [%2];"
                 : "=r"(r[0]), "=r"(r[1]) : "r"(addr));
}
__device__ __forceinline__ void mma_bf16(float* c, const uint32_t* a, const uint32_t* b) {
    asm volatile(
        "mma.sync.aligned.m16n8k16.row.col.f32.bf16.bf16.f32 "
        "{%0,%1,%2,%3}, {%4,%5,%6,%7}, {%8,%9}, {%0,%1,%2,%3};"
        : "+f"(c[0]), "+f"(c[1]), "+f"(c[2]), "+f"(c[3])
        : "r"(a[0]), "r"(a[1]), "r"(a[2]), "r"(a[3]), "r"(b[0]), "r"(b[1]));
}

template<int BN, int SK, int EPI>
__global__ void __launch_bounds__(256, 2) gemm_bf16x3(
    const __nv_bfloat16* __restrict__ Ahi, const __nv_bfloat16* __restrict__ Alo,
    const __nv_bfloat16* __restrict__ Bhi, const __nv_bfloat16* __restrict__ Blo,
    const float* __restrict__ bias, float* __restrict__ C,
    __half* __restrict__ C2,
    int M, int N, int K)
{
    constexpr int NI = BN / 32;
    constexpr int BMB = BN * ROWB;
    constexpr int STAGE = 2 * AMATB + 2 * BMB;
    constexpr int NT4 = (256 + 2 * BN) / 64;

    extern __shared__ char smem[];
    const uint32_t sb = smem_u32(smem);
    const int tid = threadIdx.x;
    const int wid = tid >> 5;
    const int lane = tid & 31;
    const int bm = blockIdx.y * 128;
    const int bn = blockIdx.x * BN;
    const int wm = (wid & 1) * 64;
    const int wn = (wid >> 1) * (BN / 4);
    const int kslice = (SK > 1) ? blockIdx.z : 0;
    const int Keff = K / SK;
    const int kbase = kslice * Keff;

    const __nv_bfloat16* gAhi = Ahi + (size_t)bm * K + kbase;
    const __nv_bfloat16* gAlo = Alo + (size_t)bm * K + kbase;
    const __nv_bfloat16* gBhi = Bhi + (size_t)bn * K + kbase;
    const __nv_bfloat16* gBlo = Blo + (size_t)bn * K + kbase;

    float acc[4][NI][4];
#pragma unroll
    for (int mi = 0; mi < 4; mi++)
#pragma unroll
        for (int ni = 0; ni < NI; ni++)
#pragma unroll
            for (int e = 0; e < 4; e++) acc[mi][ni][e] = 0.f;

    const int nch = Keff / BK;

    auto load_stage = [&](int buf, int k0) {
        const uint32_t st = sb + buf * STAGE;
#pragma unroll
        for (int it = 0; it < NT4; it++) {
            const int f = tid + it * 256;
            const int r = f >> 2;
            const int c = f & 3;
            const __nv_bfloat16* src;
            uint32_t dst;
            if (r < 128)          { src = gAhi + (size_t)r * K;
                                    dst = st + r * ROWB; }
            else if (r < 256)     { src = gAlo + (size_t)(r - 128) * K;
                                    dst = st + AMATB + (r - 128) * ROWB; }
            else if (r < 256 + BN){ src = gBhi + (size_t)(r - 256) * K;
                                    dst = st + 2 * AMATB + (r - 256) * ROWB; }
            else                  { src = gBlo + (size_t)(r - 256 - BN) * K;
                                    dst = st + 2 * AMATB + BMB + (r - 256 - BN) * ROWB; }
            cp16(dst + c * 16, src + k0 + c * 8);
        }
    };

    const int a_r  = wm + (lane & 15);
    const int a_k  = (lane >> 4) * 8;
    const int b_nr = (lane & 7) + ((lane >> 4) & 1) * 8;
    const int b_k  = ((lane >> 3) & 1) * 8;

    load_stage(0, 0);
    cp_commit();

    for (int ch = 0; ch < nch; ch++) {
        cp_wait0();
        __syncthreads();
        if (ch + 1 < nch) {
            load_stage((ch + 1) & 1, (ch + 1) * BK);
            cp_commit();
        }

        const uint32_t st = sb + (ch & 1) * STAGE;
#pragma unroll
        for (int kk = 0; kk < 2; kk++) {
            uint32_t bh[NI][2], bl[NI][2];
            const uint32_t bb = st + 2 * AMATB + (uint32_t)((kk * 16 + b_k) * 2);
#pragma unroll
            for (int p = 0; p < NI / 2; p++) {
                uint32_t rh[4], rl[4];
                const uint32_t addr = bb + (wn + p * 16 + b_nr) * ROWB;
                ldmx4(rh, addr);
                ldmx4(rl, addr + BMB);
                bh[2 * p][0] = rh[0]; bh[2 * p][1] = rh[1];
                bh[2 * p + 1][0] = rh[2]; bh[2 * p + 1][1] = rh[3];
                bl[2 * p][0] = rl[0]; bl[2 * p][1] = rl[1];
                bl[2 * p + 1][0] = rl[2]; bl[2 * p + 1][1] = rl[3];
            }
            if (NI & 1) {
                const uint32_t addr = st + 2 * AMATB
                    + (uint32_t)((wn + (NI - 1) * 8 + (lane & 7)) * ROWB
                                 + (kk * 16 + b_k) * 2);
                ldmx2(bh[NI - 1], addr);
                ldmx2(bl[NI - 1], addr + BMB);
            }
            const uint32_t ab = st + (uint32_t)(a_r * ROWB + (kk * 16 + a_k) * 2);
#pragma unroll
            for (int mi = 0; mi < 4; mi++) {
                uint32_t ah[4], al[4];
                ldmx4(ah, ab + mi * 16 * ROWB);
                ldmx4(al, ab + AMATB + mi * 16 * ROWB);
#pragma unroll
                for (int ni = 0; ni < NI; ni++) {
                    mma_bf16(acc[mi][ni], ah, bh[ni]);
                    mma_bf16(acc[mi][ni], ah, bl[ni]);
                    mma_bf16(acc[mi][ni], al, bh[ni]);
                }
            }
        }
    }

    const int g = lane >> 2;
    const int tg = lane & 3;
#pragma unroll
    for (int mi = 0; mi < 4; mi++) {
        const int r0 = bm + wm + mi * 16 + g;
#pragma unroll
        for (int ni = 0; ni < NI; ni++) {
            const int col = bn + wn + ni * 8 + tg * 2;
            const float2 bv = *(const float2*)(bias + col);
            const float a0 = acc[mi][ni][0] + bv.x;
            const float a1 = acc[mi][ni][1] + bv.y;
            const float a2 = acc[mi][ni][2] + bv.x;
            const float a3 = acc[mi][ni][3] + bv.y;
            if (EPI == 1) {
                if (col < DIM) {     // q -> fp32, stride DIM
                    float2 o0, o1;
                    o0.x = a0; o0.y = a1;
                    o1.x = a2; o1.y = a3;
                    *(float2*)(C + (size_t)r0 * DIM + col) = o0;
                    *(float2*)(C + (size_t)(r0 + 8) * DIM + col) = o1;
                } else {             // k|v -> fp16, stride 1024
                    const int c2 = col - DIM;
                    float2 t0; t0.x = a0; t0.y = a1;
                    float2 t1; t1.x = a2; t1.y = a3;
                    __half2 o0 = __float22half2_rn(t0);
                    __half2 o1 = __float22half2_rn(t1);
                    *(__half2*)(C2 + (size_t)r0 * 1024 + c2) = o0;
                    *(__half2*)(C2 + (size_t)(r0 + 8) * 1024 + c2) = o1;
                }
            } else if (SK == 1) {
                float2 o0, o1;
                o0.x = a0; o0.y = a1;
                o1.x = a2; o1.y = a3;
                *(float2*)(C + (size_t)r0 * N + col) = o0;
                *(float2*)(C + (size_t)(r0 + 8) * N + col) = o1;
            } else {
                const float bx = (kslice == 0) ? 0.f : bv.x;
                const float by = (kslice == 0) ? 0.f : bv.y;
                float* p0 = C + (size_t)r0 * N + col;
                float* p1 = C + (size_t)(r0 + 8) * N + col;
                atomicAdd(p0,     a0 - bx);
                atomicAdd(p0 + 1, a1 - by);
                atomicAdd(p1,     a2 - bx);
                atomicAdd(p1 + 1, a3 - by);
            }
        }
    }
}

#define GEMM_SMEM_96  (2 * (2 * AMATB + 2 * 96 * ROWB))
#define GEMM_SMEM_128 (2 * (2 * AMATB + 2 * 128 * ROWB))

// ---------------------------------------------------------------------------
// Neighborhood attention: one warp per (pixel, head). q fp32, k/v fp16.
// Score phase: half-warp per neighbor, uint2 (4 fp16) loads, 4 shfls / 2 nbrs.
// Probs parked in smem; AV via half2 loads. bf16 hi/lo epilogue.
// ---------------------------------------------------------------------------
__global__ void __launch_bounds__(256) nat_attn(
    const float* __restrict__ q, const __half* __restrict__ kvh,
    const float* __restrict__ rpb,
    __nv_bfloat16* __restrict__ ahi, __nv_bfloat16* __restrict__ alo)
{
    __shared__ float sprob[8][52];

    const int warp = threadIdx.x >> 5;
    const int lane = threadIdx.x & 31;
    const int j = blockIdx.x * 8 + warp;
    const int i = blockIdx.y;
    const int h = blockIdx.z;
    const int pix = i * HWDIM + j;

    const int sh = min(max(i - 3, 0), HWDIM - KWIN);
    const int sw = min(max(j - 3, 0), HWDIM - KWIN);

    const int half_ = lane >> 4;
    const int l15 = lane & 15;

    float4 q4 = ((const float4*)(q + (size_t)pix * DIM + h * HD))[l15];
    q4.x *= 0.125f; q4.y *= 0.125f; q4.z *= 0.125f; q4.w *= 0.125f;

    const float* rp = rpb + h * 169 + (sh - i + 6) * 13 + (sw - j + 6);
    const __half* kb = kvh + (size_t)(sh * HWDIM + sw) * 1024 + h * HD;

#pragma unroll
    for (int it = 0; it < 25; it++) {
        const int t = 2 * it + half_;
        const bool valid = (t < 49);
        const int tt = valid ? t : 0;
        const unsigned a = ((unsigned)tt * 37u) >> 8;
        const int c = tt - 7 * (int)a;
        const uint2 kr = *(const uint2*)(kb + ((size_t)a * HWDIM + c) * 1024 + l15 * 4);
        const float2 f0 = __half22float2(*(const __half2*)&kr.x);
        const float2 f1 = __half22float2(*(const __half2*)&kr.y);
        float s = q4.x * f0.x + q4.y * f0.y + q4.z * f1.x + q4.w * f1.y;
        s += __shfl_xor_sync(0xffffffffu, s, 1);
        s += __shfl_xor_sync(0xffffffffu, s, 2);
        s += __shfl_xor_sync(0xffffffffu, s, 4);
        s += __shfl_xor_sync(0xffffffffu, s, 8);
        if (l15 == 0 && valid)
            sprob[warp][t] = s + rp[a * 13 + c];
    }
    __syncwarp();

    float s0 = sprob[warp][lane];
    float s1 = (lane + 32 < 49) ? sprob[warp][lane + 32] : -1e30f;
    float m = fmaxf(s0, s1);
#pragma unroll
    for (int o = 16; o; o >>= 1)
        m = fmaxf(m, __shfl_xor_sync(0xffffffffu, m, o));
    float e0 = __expf(s0 - m);
    float e1 = (lane + 32 < 49) ? __expf(s1 - m) : 0.f;
    float sum = e0 + e1;
#pragma unroll
    for (int o = 16; o; o >>= 1)
        sum += __shfl_xor_sync(0xffffffffu, sum, o);
    const float inv = __fdividef(1.f, sum);
    sprob[warp][lane] = e0 * inv;
    if (lane + 32 < 49) sprob[warp][lane + 32] = e1 * inv;
    __syncwarp();

    float ax = 0.f, ay = 0.f;
    const __half* vb = kvh + (size_t)(sh * HWDIM + sw) * 1024 + 512 + h * HD;
#pragma unroll
    for (int a = 0; a < KWIN; a++) {
#pragma unroll
        for (int c = 0; c < KWIN; c++) {
            const float at = sprob[warp][a * 7 + c];
            const __half2 vv =
                *(const __half2*)(vb + ((size_t)a * HWDIM + c) * 1024 + 2 * lane);
            const float2 f = __half22float2(vv);
            ax = fmaf(at, f.x, ax);
            ay = fmaf(at, f.y, ay);
        }
    }

    __nv_bfloat16 hx = __float2bfloat16(ax);
    __nv_bfloat16 hy = __float2bfloat16(ay);
    __nv_bfloat16 lx = __float2bfloat16(ax - __bfloat162float(hx));
    __nv_bfloat16 ly = __float2bfloat16(ay - __bfloat162float(hy));
    const size_t oidx = (size_t)pix * DIM + h * HD + 2 * lane;
    __nv_bfloat162 ph(hx, hy), pl(lx, ly);
    *(__nv_bfloat162*)(ahi + oidx) = ph;
    *(__nv_bfloat162*)(alo + oidx) = pl;
}

// ---------------------------------------------------------------------------
extern "C" void kernel_launch(void* const* d_in, const int* in_sizes, int n_in,
                              void* d_out, int out_size)
{
    const float* x      = (const float*)d_in[0];
    const float* qkv_w  = (const float*)d_in[1];
    const float* qkv_b  = (const float*)d_in[2];
    const float* rpb    = (const float*)d_in[3];
    const float* proj_w = (const float*)d_in[4];
    const float* proj_b = (const float*)d_in[5];
    float* out = (float*)d_out;

    float *q;
    __half *kvh;
    __nv_bfloat16 *xhi, *xlo, *w1hi, *w1lo, *ahi, *alo, *w2hi, *w2lo;
    cudaGetSymbolAddress((void**)&q, g_q);
    cudaGetSymbolAddress((void**)&kvh, g_kvh);
    cudaGetSymbolAddress((void**)&xhi, g_xhi);
    cudaGetSymbolAddress((void**)&xlo, g_xlo);
    cudaGetSymbolAddress((void**)&w1hi, g_w1hi);
    cudaGetSymbolAddress((void**)&w1lo, g_w1lo);
    cudaGetSymbolAddress((void**)&ahi, g_ahi);
    cudaGetSymbolAddress((void**)&alo, g_alo);
    cudaGetSymbolAddress((void**)&w2hi, g_w2hi);
    cudaGetSymbolAddress((void**)&w2lo, g_w2lo);

    cudaFuncSetAttribute((const void*)gemm_bf16x3<96, 1, 1>,
                         cudaFuncAttributeMaxDynamicSharedMemorySize, GEMM_SMEM_96);
    cudaFuncSetAttribute((const void*)gemm_bf16x3<128, 2, 0>,
                         cudaFuncAttributeMaxDynamicSharedMemorySize, GEMM_SMEM_128);

    // 0) Zero the split-K target + split fp32 inputs into bf16 hi/lo
    zero_out<<<NPIX * DIM / 1024, 256>>>(out);
    cvt_all<<<(N_X + N_W1 + N_W2) / 1024, 256>>>(
        x, qkv_w, proj_w, xhi, xlo, w1hi, w1lo, w2hi, w2lo);

    // 1) QKV projection: q -> fp32, k|v -> fp16 (split epilogue)
    gemm_bf16x3<96, 1, 1><<<dim3(QKVN / 96, NPIX / 128), 256, GEMM_SMEM_96>>>(
        xhi, xlo, w1hi, w1lo, qkv_b, q, kvh, NPIX, QKVN, DIM);

    // 2) Neighborhood attention (fp16 k/v; emits bf16 hi/lo directly)
    nat_attn<<<dim3(HWDIM / 8, HWDIM, NHEAD), 256>>>(q, kvh, rpb, ahi, alo);

    // 3) Output projection: 128x128 tiles, split-K=2 (400 CTAs)
    gemm_bf16x3<128, 2, 0><<<dim3(DIM / 128, NPIX / 128, 2), 256, GEMM_SMEM_128>>>(
        ahi, alo, w2hi, w2lo, proj_b, out, nullptr, NPIX, DIM, DIM);
}

// round 13
// speedup vs baseline: 1.4067x; 1.2699x over previous
#include <cuda_runtime.h>
#include <cuda_bf16.h>
#include <cuda_fp16.h>
#include <cstdint>
#include <math.h>

// Problem constants
#define HWDIM 80
#define NPIX  6400
#define DIM   512
#define QKVN  1536
#define NHEAD 8
#define HD    64
#define KWIN  7

// Scratch (allocation-free rule: __device__ globals)
__device__ float g_q[(size_t)NPIX * DIM];          // q fp32
__device__ __half g_kvh[(size_t)NPIX * 1024];      // k|v fp16
__device__ __half g_xh[(size_t)NPIX * DIM];        // x fp16
__device__ __half g_w1h[(size_t)QKVN * DIM];       // qkv_w fp16 hi
__device__ __half g_w1l[(size_t)QKVN * DIM];       // qkv_w fp16 lo
__device__ __half g_ao[(size_t)NPIX * DIM];        // attn out fp16
__device__ __half g_w2h[(size_t)DIM * DIM];        // proj_w fp16 hi
__device__ __half g_w2l[(size_t)DIM * DIM];        // proj_w fp16 lo

#define N_X  (NPIX * DIM)
#define N_W1 (QKVN * DIM)
#define N_W2 (DIM * DIM)

__device__ __forceinline__ uint32_t smem_u32(const void* p) {
    uint32_t a;
    asm("{ .reg .u64 t; cvta.to.shared.u64 t, %1; cvt.u32.u64 %0, t; }"
        : "=r"(a) : "l"(p));
    return a;
}
__device__ __forceinline__ void cp16(uint32_t dst, const void* src) {
    asm volatile("cp.async.cg.shared.global [%0], [%1], 16;"
                 :: "r"(dst), "l"(src));
}
__device__ __forceinline__ void cp_commit() {
    asm volatile("cp.async.commit_group;" ::: "memory");
}
__device__ __forceinline__ void cp_wait0() {
    asm volatile("cp.async.wait_group 0;" ::: "memory");
}

// ---------------------------------------------------------------------------
// Zero-init for the split-K accumulation target.
// ---------------------------------------------------------------------------
__global__ void __launch_bounds__(256) zero_out(float* __restrict__ p)
{
    const int i = (blockIdx.x * 256 + threadIdx.x) * 4;
    float4 z; z.x = 0.f; z.y = 0.f; z.z = 0.f; z.w = 0.f;
    *(float4*)(p + i) = z;
}

// ---------------------------------------------------------------------------
// Convert inputs: x -> fp16; qkv_w, proj_w -> fp16 hi/lo. One launch.
// ---------------------------------------------------------------------------
__global__ void __launch_bounds__(256) cvt_all(
    const float* __restrict__ x, const float* __restrict__ w1,
    const float* __restrict__ w2,
    __half* __restrict__ xh,
    __half* __restrict__ w1h, __half* __restrict__ w1l,
    __half* __restrict__ w2h, __half* __restrict__ w2l)
{
    int i = (blockIdx.x * 256 + threadIdx.x) * 4;
    if (i < N_X) {
        float4 v = *(const float4*)(x + i);
        __half2 h0 = __floats2half2_rn(v.x, v.y);
        __half2 h1 = __floats2half2_rn(v.z, v.w);
        uint2 o; o.x = *(uint32_t*)&h0; o.y = *(uint32_t*)&h1;
        *(uint2*)(xh + i) = o;
        return;
    }
    const float* src;
    __half *hi, *lo;
    if (i < N_X + N_W1) { i -= N_X;        src = w1 + i; hi = w1h + i; lo = w1l + i; }
    else                { i -= N_X + N_W1; src = w2 + i; hi = w2h + i; lo = w2l + i; }

    float4 v = *(const float4*)src;
    float f[4] = {v.x, v.y, v.z, v.w};
    __half h[4], l[4];
#pragma unroll
    for (int k = 0; k < 4; k++) {
        h[k] = __float2half(f[k]);
        l[k] = __float2half(f[k] - __half2float(h[k]));
    }
    uint2 ph, pl;
    {
        __half2 t;
        t = __halves2half2(h[0], h[1]); ph.x = *(uint32_t*)&t;
        t = __halves2half2(h[2], h[3]); ph.y = *(uint32_t*)&t;
        t = __halves2half2(l[0], l[1]); pl.x = *(uint32_t*)&t;
        t = __halves2half2(l[2], l[3]); pl.y = *(uint32_t*)&t;
    }
    *(uint2*)hi = ph;
    *(uint2*)lo = pl;
}

// ---------------------------------------------------------------------------
// mma.sync fp16x2 GEMM: C = A @ (Bhi + Blo)^T + bias
// A plain fp16; B fp16 hi/lo (2 MMAs per fragment pair).
// 128 x BN CTA tile, 256 threads = 8 warps in 2(m) x 4(n); warp 64 x (BN/4).
// EPI=0: fp32 C (SK-way split-K via atomics when SK>1).
// EPI=1: QKV split epilogue — cols [0,512) fp32 -> C (stride 512),
//                             cols [512,1536) fp16 -> C2 (stride 1024).
// ---------------------------------------------------------------------------
#define BK 32
#define ROWB 80
#define AMATB (128 * ROWB)

__device__ __forceinline__ void ldmx4(uint32_t* r, uint32_t addr) {
    asm volatile("ldmatrix.sync.aligned.m8n8.x4.shared.b16 {%0,%1,%2,%3}, [%4];"
                 : "=r"(r[0]), "=r"(r[1]), "=r"(r[2]), "=r"(r[3]) : "r"(addr));
}
__device__ __forceinline__ void ldmx2(uint32_t* r, uint32_t addr) {
    asm volatile("ldmatrix.sync.aligned.m8n8.x2.shared.b16 {%0,%1}, [%2];"
                 : "=r"(r[0]), "=r"(r[1]) : "r"(addr));
}
__device__ __forceinline__ void mma_f16(float* c, const uint32_t* a, const uint32_t* b) {
    asm volatile(
        "mma.sync.aligned.m16n8k16.row.col.f32.f16.f16.f32 "
        "{%0,%1,%2,%3}, {%4,%5,%6,%7}, {%8,%9}, {%0,%1,%2,%3};"
        : "+f"(c[0]), "+f"(c[1]), "+f"(c[2]), "+f"(c[3])
        : "r"(a[0]), "r"(a[1]), "r"(a[2]), "r"(a[3]), "r"(b[0]), "r"(b[1]));
}

template<int BN, int SK, int EPI>
__global__ void __launch_bounds__(256, 2) gemm_f16x2(
    const __half* __restrict__ A,
    const __half* __restrict__ Bhi, const __half* __restrict__ Blo,
    const float* __restrict__ bias, float* __restrict__ C,
    __half* __restrict__ C2,
    int M, int N, int K)
{
    constexpr int NI = BN / 32;
    constexpr int BMB = BN * ROWB;
    constexpr int STAGE = AMATB + 2 * BMB;
    constexpr int NT4 = (128 + 2 * BN) / 64;   // cp16 per thread per stage

    extern __shared__ char smem[];
    const uint32_t sb = smem_u32(smem);
    const int tid = threadIdx.x;
    const int wid = tid >> 5;
    const int lane = tid & 31;
    const int bm = blockIdx.y * 128;
    const int bn = blockIdx.x * BN;
    const int wm = (wid & 1) * 64;
    const int wn = (wid >> 1) * (BN / 4);
    const int kslice = (SK > 1) ? blockIdx.z : 0;
    const int Keff = K / SK;
    const int kbase = kslice * Keff;

    const __half* gA   = A   + (size_t)bm * K + kbase;
    const __half* gBhi = Bhi + (size_t)bn * K + kbase;
    const __half* gBlo = Blo + (size_t)bn * K + kbase;

    float acc[4][NI][4];
#pragma unroll
    for (int mi = 0; mi < 4; mi++)
#pragma unroll
        for (int ni = 0; ni < NI; ni++)
#pragma unroll
            for (int e = 0; e < 4; e++) acc[mi][ni][e] = 0.f;

    const int nch = Keff / BK;

    auto load_stage = [&](int buf, int k0) {
        const uint32_t st = sb + buf * STAGE;
#pragma unroll
        for (int it = 0; it < NT4; it++) {
            const int f = tid + it * 256;
            const int r = f >> 2;
            const int c = f & 3;
            const __half* src;
            uint32_t dst;
            if (r < 128)          { src = gA + (size_t)r * K;
                                    dst = st + r * ROWB; }
            else if (r < 128 + BN){ src = gBhi + (size_t)(r - 128) * K;
                                    dst = st + AMATB + (r - 128) * ROWB; }
            else                  { src = gBlo + (size_t)(r - 128 - BN) * K;
                                    dst = st + AMATB + BMB + (r - 128 - BN) * ROWB; }
            cp16(dst + c * 16, src + k0 + c * 8);
        }
    };

    const int a_r  = wm + (lane & 15);
    const int a_k  = (lane >> 4) * 8;
    const int b_nr = (lane & 7) + ((lane >> 4) & 1) * 8;
    const int b_k  = ((lane >> 3) & 1) * 8;

    load_stage(0, 0);
    cp_commit();

    for (int ch = 0; ch < nch; ch++) {
        cp_wait0();
        __syncthreads();
        if (ch + 1 < nch) {
            load_stage((ch + 1) & 1, (ch + 1) * BK);
            cp_commit();
        }

        const uint32_t st = sb + (ch & 1) * STAGE;
#pragma unroll
        for (int kk = 0; kk < 2; kk++) {
            uint32_t bh[NI][2], bl[NI][2];
            const uint32_t bb = st + AMATB + (uint32_t)((kk * 16 + b_k) * 2);
#pragma unroll
            for (int p = 0; p < NI / 2; p++) {
                uint32_t rh[4], rl[4];
                const uint32_t addr = bb + (wn + p * 16 + b_nr) * ROWB;
                ldmx4(rh, addr);
                ldmx4(rl, addr + BMB);
                bh[2 * p][0] = rh[0]; bh[2 * p][1] = rh[1];
                bh[2 * p + 1][0] = rh[2]; bh[2 * p + 1][1] = rh[3];
                bl[2 * p][0] = rl[0]; bl[2 * p][1] = rl[1];
                bl[2 * p + 1][0] = rl[2]; bl[2 * p + 1][1] = rl[3];
            }
            if (NI & 1) {
                const uint32_t addr = st + AMATB
                    + (uint32_t)((wn + (NI - 1) * 8 + (lane & 7)) * ROWB
                                 + (kk * 16 + b_k) * 2);
                ldmx2(bh[NI - 1], addr);
                ldmx2(bl[NI - 1], addr + BMB);
            }
            const uint32_t ab = st + (uint32_t)(a_r * ROWB + (kk * 16 + a_k) * 2);
#pragma unroll
            for (int mi = 0; mi < 4; mi++) {
                uint32_t af[4];
                ldmx4(af, ab + mi * 16 * ROWB);
#pragma unroll
                for (int ni = 0; ni < NI; ni++) {
                    mma_f16(acc[mi][ni], af, bh[ni]);
                    mma_f16(acc[mi][ni], af, bl[ni]);
                }
            }
        }
    }

    const int g = lane >> 2;
    const int tg = lane & 3;
#pragma unroll
    for (int mi = 0; mi < 4; mi++) {
        const int r0 = bm + wm + mi * 16 + g;
#pragma unroll
        for (int ni = 0; ni < NI; ni++) {
            const int col = bn + wn + ni * 8 + tg * 2;
            const float2 bv = *(const float2*)(bias + col);
            const float a0 = acc[mi][ni][0] + bv.x;
            const float a1 = acc[mi][ni][1] + bv.y;
            const float a2 = acc[mi][ni][2] + bv.x;
            const float a3 = acc[mi][ni][3] + bv.y;
            if (EPI == 1) {
                if (col < DIM) {     // q -> fp32, stride DIM
                    float2 o0, o1;
                    o0.x = a0; o0.y = a1;
                    o1.x = a2; o1.y = a3;
                    *(float2*)(C + (size_t)r0 * DIM + col) = o0;
                    *(float2*)(C + (size_t)(r0 + 8) * DIM + col) = o1;
                } else {             // k|v -> fp16, stride 1024
                    const int c2 = col - DIM;
                    __half2 o0 = __floats2half2_rn(a0, a1);
                    __half2 o1 = __floats2half2_rn(a2, a3);
                    *(__half2*)(C2 + (size_t)r0 * 1024 + c2) = o0;
                    *(__half2*)(C2 + (size_t)(r0 + 8) * 1024 + c2) = o1;
                }
            } else if (SK == 1) {
                float2 o0, o1;
                o0.x = a0; o0.y = a1;
                o1.x = a2; o1.y = a3;
                *(float2*)(C + (size_t)r0 * N + col) = o0;
                *(float2*)(C + (size_t)(r0 + 8) * N + col) = o1;
            } else {
                const float bx = (kslice == 0) ? 0.f : bv.x;
                const float by = (kslice == 0) ? 0.f : bv.y;
                float* p0 = C + (size_t)r0 * N + col;
                float* p1 = C + (size_t)(r0 + 8) * N + col;
                atomicAdd(p0,     a0 - bx);
                atomicAdd(p0 + 1, a1 - by);
                atomicAdd(p1,     a2 - bx);
                atomicAdd(p1 + 1, a3 - by);
            }
        }
    }
}

#define GEMM_SMEM_96  (2 * (AMATB + 2 * 96 * ROWB))    // 51200
#define GEMM_SMEM_128 (2 * (AMATB + 2 * 128 * ROWB))   // 61440

// ---------------------------------------------------------------------------
// Neighborhood attention: one warp per (pixel, head). q fp32, k/v fp16.
// Score phase: half-warp per neighbor, uint2 (4 fp16) loads, 4 shfls / 2 nbrs.
// Probs parked in smem; AV via half2 loads. fp16 output.
// ---------------------------------------------------------------------------
__global__ void __launch_bounds__(256) nat_attn(
    const float* __restrict__ q, const __half* __restrict__ kvh,
    const float* __restrict__ rpb,
    __half* __restrict__ ao)
{
    __shared__ float sprob[8][52];

    const int warp = threadIdx.x >> 5;
    const int lane = threadIdx.x & 31;
    const int j = blockIdx.x * 8 + warp;
    const int i = blockIdx.y;
    const int h = blockIdx.z;
    const int pix = i * HWDIM + j;

    const int sh = min(max(i - 3, 0), HWDIM - KWIN);
    const int sw = min(max(j - 3, 0), HWDIM - KWIN);

    const int half_ = lane >> 4;
    const int l15 = lane & 15;

    float4 q4 = ((const float4*)(q + (size_t)pix * DIM + h * HD))[l15];
    q4.x *= 0.125f; q4.y *= 0.125f; q4.z *= 0.125f; q4.w *= 0.125f;

    const float* rp = rpb + h * 169 + (sh - i + 6) * 13 + (sw - j + 6);
    const __half* kb = kvh + (size_t)(sh * HWDIM + sw) * 1024 + h * HD;

#pragma unroll
    for (int it = 0; it < 25; it++) {
        const int t = 2 * it + half_;
        const bool valid = (t < 49);
        const int tt = valid ? t : 0;
        const unsigned a = ((unsigned)tt * 37u) >> 8;
        const int c = tt - 7 * (int)a;
        const uint2 kr = *(const uint2*)(kb + ((size_t)a * HWDIM + c) * 1024 + l15 * 4);
        const float2 f0 = __half22float2(*(const __half2*)&kr.x);
        const float2 f1 = __half22float2(*(const __half2*)&kr.y);
        float s = q4.x * f0.x + q4.y * f0.y + q4.z * f1.x + q4.w * f1.y;
        s += __shfl_xor_sync(0xffffffffu, s, 1);
        s += __shfl_xor_sync(0xffffffffu, s, 2);
        s += __shfl_xor_sync(0xffffffffu, s, 4);
        s += __shfl_xor_sync(0xffffffffu, s, 8);
        if (l15 == 0 && valid)
            sprob[warp][t] = s + rp[a * 13 + c];
    }
    __syncwarp();

    float s0 = sprob[warp][lane];
    float s1 = (lane + 32 < 49) ? sprob[warp][lane + 32] : -1e30f;
    float m = fmaxf(s0, s1);
#pragma unroll
    for (int o = 16; o; o >>= 1)
        m = fmaxf(m, __shfl_xor_sync(0xffffffffu, m, o));
    float e0 = __expf(s0 - m);
    float e1 = (lane + 32 < 49) ? __expf(s1 - m) : 0.f;
    float sum = e0 + e1;
#pragma unroll
    for (int o = 16; o; o >>= 1)
        sum += __shfl_xor_sync(0xffffffffu, sum, o);
    const float inv = __fdividef(1.f, sum);
    sprob[warp][lane] = e0 * inv;
    if (lane + 32 < 49) sprob[warp][lane + 32] = e1 * inv;
    __syncwarp();

    float ax = 0.f, ay = 0.f;
    const __half* vb = kvh + (size_t)(sh * HWDIM + sw) * 1024 + 512 + h * HD;
#pragma unroll
    for (int a = 0; a < KWIN; a++) {
#pragma unroll
        for (int c = 0; c < KWIN; c++) {
            const float at = sprob[warp][a * 7 + c];
            const __half2 vv =
                *(const __half2*)(vb + ((size_t)a * HWDIM + c) * 1024 + 2 * lane);
            const float2 f = __half22float2(vv);
            ax = fmaf(at, f.x, ax);
            ay = fmaf(at, f.y, ay);
        }
    }

    __half2 o = __floats2half2_rn(ax, ay);
    *(__half2*)(ao + (size_t)pix * DIM + h * HD + 2 * lane) = o;
}

// ---------------------------------------------------------------------------
extern "C" void kernel_launch(void* const* d_in, const int* in_sizes, int n_in,
                              void* d_out, int out_size)
{
    const float* x      = (const float*)d_in[0];
    const float* qkv_w  = (const float*)d_in[1];
    const float* qkv_b  = (const float*)d_in[2];
    const float* rpb    = (const float*)d_in[3];
    const float* proj_w = (const float*)d_in[4];
    const float* proj_b = (const float*)d_in[5];
    float* out = (float*)d_out;

    float *q;
    __half *kvh, *xh, *w1h, *w1l, *ao, *w2h, *w2l;
    cudaGetSymbolAddress((void**)&q, g_q);
    cudaGetSymbolAddress((void**)&kvh, g_kvh);
    cudaGetSymbolAddress((void**)&xh, g_xh);
    cudaGetSymbolAddress((void**)&w1h, g_w1h);
    cudaGetSymbolAddress((void**)&w1l, g_w1l);
    cudaGetSymbolAddress((void**)&ao, g_ao);
    cudaGetSymbolAddress((void**)&w2h, g_w2h);
    cudaGetSymbolAddress((void**)&w2l, g_w2l);

    cudaFuncSetAttribute((const void*)gemm_f16x2<96, 1, 1>,
                         cudaFuncAttributeMaxDynamicSharedMemorySize, GEMM_SMEM_96);
    cudaFuncSetAttribute((const void*)gemm_f16x2<128, 2, 0>,
                         cudaFuncAttributeMaxDynamicSharedMemorySize, GEMM_SMEM_128);

    // 0) Zero the split-K target + convert inputs
    zero_out<<<NPIX * DIM / 1024, 256>>>(out);
    cvt_all<<<(N_X + N_W1 + N_W2) / 1024, 256>>>(
        x, qkv_w, proj_w, xh, w1h, w1l, w2h, w2l);

    // 1) QKV projection: q -> fp32, k|v -> fp16 (split epilogue)
    gemm_f16x2<96, 1, 1><<<dim3(QKVN / 96, NPIX / 128), 256, GEMM_SMEM_96>>>(
        xh, w1h, w1l, qkv_b, q, kvh, NPIX, QKVN, DIM);

    // 2) Neighborhood attention (fp16 k/v; fp16 output)
    nat_attn<<<dim3(HWDIM / 8, HWDIM, NHEAD), 256>>>(q, kvh, rpb, ao);

    // 3) Output projection: 128x128 tiles, split-K=2 (400 CTAs)
    gemm_f16x2<128, 2, 0><<<dim3(DIM / 128, NPIX / 128, 2), 256, GEMM_SMEM_128>>>(
        ao, w2h, w2l, proj_b, out, nullptr, NPIX, DIM, DIM);
}

// round 14
// speedup vs baseline: 1.7633x; 1.2535x over previous
#include <cuda_runtime.h>
#include <cuda_bf16.h>
#include <cuda_fp16.h>
#include <cstdint>
#include <math.h>

// Problem constants
#define HWDIM 80
#define NPIX  6400
#define DIM   512
#define QKVN  1536
#define NHEAD 8
#define HD    64
#define KWIN  7

// Scratch (allocation-free rule: __device__ globals)
__device__ float g_q[(size_t)NPIX * DIM];          // q fp32
__device__ __half g_kvh[(size_t)NPIX * 1024];      // k|v fp16
__device__ __half g_xh[(size_t)NPIX * DIM];        // x fp16
__device__ __half g_w1h[(size_t)QKVN * DIM];       // qkv_w fp16
__device__ __half g_ao[(size_t)NPIX * DIM];        // attn out fp16
__device__ __half g_w2h[(size_t)DIM * DIM];        // proj_w fp16

#define N_X  (NPIX * DIM)
#define N_W1 (QKVN * DIM)
#define N_W2 (DIM * DIM)

__device__ __forceinline__ uint32_t smem_u32(const void* p) {
    uint32_t a;
    asm("{ .reg .u64 t; cvta.to.shared.u64 t, %1; cvt.u32.u64 %0, t; }"
        : "=r"(a) : "l"(p));
    return a;
}
__device__ __forceinline__ void cp16(uint32_t dst, const void* src) {
    asm volatile("cp.async.cg.shared.global [%0], [%1], 16;"
                 :: "r"(dst), "l"(src));
}
__device__ __forceinline__ void cp_commit() {
    asm volatile("cp.async.commit_group;" ::: "memory");
}
__device__ __forceinline__ void cp_wait0() {
    asm volatile("cp.async.wait_group 0;" ::: "memory");
}

// ---------------------------------------------------------------------------
// Zero-init for the split-K accumulation target.
// ---------------------------------------------------------------------------
__global__ void __launch_bounds__(256) zero_out(float* __restrict__ p)
{
    const int i = (blockIdx.x * 256 + threadIdx.x) * 4;
    float4 z; z.x = 0.f; z.y = 0.f; z.z = 0.f; z.w = 0.f;
    *(float4*)(p + i) = z;
}

// ---------------------------------------------------------------------------
// Convert inputs: x, qkv_w, proj_w -> plain fp16. One launch.
// ---------------------------------------------------------------------------
__global__ void __launch_bounds__(256) cvt_all(
    const float* __restrict__ x, const float* __restrict__ w1,
    const float* __restrict__ w2,
    __half* __restrict__ xh, __half* __restrict__ w1h,
    __half* __restrict__ w2h)
{
    int i = (blockIdx.x * 256 + threadIdx.x) * 4;
    const float* src;
    __half* dst;
    if (i < N_X)              { src = x + i;             dst = xh + i; }
    else if (i < N_X + N_W1)  { i -= N_X;  src = w1 + i; dst = w1h + i; }
    else                      { i -= N_X + N_W1; src = w2 + i; dst = w2h + i; }

    float4 v = *(const float4*)src;
    __half2 h0 = __floats2half2_rn(v.x, v.y);
    __half2 h1 = __floats2half2_rn(v.z, v.w);
    uint2 o; o.x = *(uint32_t*)&h0; o.y = *(uint32_t*)&h1;
    *(uint2*)dst = o;
}

// ---------------------------------------------------------------------------
// mma.sync fp16 GEMM: C = A @ B^T + bias  (plain fp16 A and B, fp32 accum)
// 128 x BN CTA tile, 256 threads = 8 warps in 2(m) x 4(n); warp 64 x (BN/4).
// EPI=0: fp32 C (SK-way split-K via atomics when SK>1).
// EPI=1: QKV split epilogue — cols [0,512) fp32 -> C (stride 512),
//                             cols [512,1536) fp16 -> C2 (stride 1024).
// ---------------------------------------------------------------------------
#define BK 32
#define ROWB 80
#define AMATB (128 * ROWB)

__device__ __forceinline__ void ldmx4(uint32_t* r, uint32_t addr) {
    asm volatile("ldmatrix.sync.aligned.m8n8.x4.shared.b16 {%0,%1,%2,%3}, [%4];"
                 : "=r"(r[0]), "=r"(r[1]), "=r"(r[2]), "=r"(r[3]) : "r"(addr));
}
__device__ __forceinline__ void ldmx2(uint32_t* r, uint32_t addr) {
    asm volatile("ldmatrix.sync.aligned.m8n8.x2.shared.b16 {%0,%1}, [%2];"
                 : "=r"(r[0]), "=r"(r[1]) : "r"(addr));
}
__device__ __forceinline__ void mma_f16(float* c, const uint32_t* a, const uint32_t* b) {
    asm volatile(
        "mma.sync.aligned.m16n8k16.row.col.f32.f16.f16.f32 "
        "{%0,%1,%2,%3}, {%4,%5,%6,%7}, {%8,%9}, {%0,%1,%2,%3};"
        : "+f"(c[0]), "+f"(c[1]), "+f"(c[2]), "+f"(c[3])
        : "r"(a[0]), "r"(a[1]), "r"(a[2]), "r"(a[3]), "r"(b[0]), "r"(b[1]));
}

template<int BN, int SK, int EPI>
__global__ void __launch_bounds__(256, 2) gemm_f16(
    const __half* __restrict__ A, const __half* __restrict__ B,
    const float* __restrict__ bias, float* __restrict__ C,
    __half* __restrict__ C2,
    int M, int N, int K)
{
    constexpr int NI = BN / 32;
    constexpr int BMB = BN * ROWB;
    constexpr int STAGE = AMATB + BMB;
    constexpr int NCH16 = (128 + BN) * 4;        // 16B chunks per stage
    constexpr int NT4 = (NCH16 + 255) / 256;     // cp16 iters per thread

    extern __shared__ char smem[];
    const uint32_t sb = smem_u32(smem);
    const int tid = threadIdx.x;
    const int wid = tid >> 5;
    const int lane = tid & 31;
    const int bm = blockIdx.y * 128;
    const int bn = blockIdx.x * BN;
    const int wm = (wid & 1) * 64;
    const int wn = (wid >> 1) * (BN / 4);
    const int kslice = (SK > 1) ? blockIdx.z : 0;
    const int Keff = K / SK;
    const int kbase = kslice * Keff;

    const __half* gA = A + (size_t)bm * K + kbase;
    const __half* gB = B + (size_t)bn * K + kbase;

    float acc[4][NI][4];
#pragma unroll
    for (int mi = 0; mi < 4; mi++)
#pragma unroll
        for (int ni = 0; ni < NI; ni++)
#pragma unroll
            for (int e = 0; e < 4; e++) acc[mi][ni][e] = 0.f;

    const int nch = Keff / BK;

    auto load_stage = [&](int buf, int k0) {
        const uint32_t st = sb + buf * STAGE;
#pragma unroll
        for (int it = 0; it < NT4; it++) {
            const int f = tid + it * 256;
            if (NCH16 % 256 != 0 && f >= NCH16) break;
            const int r = f >> 2;
            const int c = f & 3;
            const __half* src;
            uint32_t dst;
            if (r < 128) { src = gA + (size_t)r * K;
                           dst = st + r * ROWB; }
            else         { src = gB + (size_t)(r - 128) * K;
                           dst = st + AMATB + (r - 128) * ROWB; }
            cp16(dst + c * 16, src + k0 + c * 8);
        }
    };

    const int a_r  = wm + (lane & 15);
    const int a_k  = (lane >> 4) * 8;
    const int b_nr = (lane & 7) + ((lane >> 4) & 1) * 8;
    const int b_k  = ((lane >> 3) & 1) * 8;

    load_stage(0, 0);
    cp_commit();

    for (int ch = 0; ch < nch; ch++) {
        cp_wait0();
        __syncthreads();
        if (ch + 1 < nch) {
            load_stage((ch + 1) & 1, (ch + 1) * BK);
            cp_commit();
        }

        const uint32_t st = sb + (ch & 1) * STAGE;
#pragma unroll
        for (int kk = 0; kk < 2; kk++) {
            uint32_t bf[NI][2];
            const uint32_t bb = st + AMATB + (uint32_t)((kk * 16 + b_k) * 2);
#pragma unroll
            for (int p = 0; p < NI / 2; p++) {
                uint32_t rr[4];
                ldmx4(rr, bb + (wn + p * 16 + b_nr) * ROWB);
                bf[2 * p][0] = rr[0]; bf[2 * p][1] = rr[1];
                bf[2 * p + 1][0] = rr[2]; bf[2 * p + 1][1] = rr[3];
            }
            if (NI & 1) {
                const uint32_t addr = st + AMATB
                    + (uint32_t)((wn + (NI - 1) * 8 + (lane & 7)) * ROWB
                                 + (kk * 16 + b_k) * 2);
                ldmx2(bf[NI - 1], addr);
            }
            const uint32_t ab = st + (uint32_t)(a_r * ROWB + (kk * 16 + a_k) * 2);
#pragma unroll
            for (int mi = 0; mi < 4; mi++) {
                uint32_t af[4];
                ldmx4(af, ab + mi * 16 * ROWB);
#pragma unroll
                for (int ni = 0; ni < NI; ni++)
                    mma_f16(acc[mi][ni], af, bf[ni]);
            }
        }
    }

    const int g = lane >> 2;
    const int tg = lane & 3;
#pragma unroll
    for (int mi = 0; mi < 4; mi++) {
        const int r0 = bm + wm + mi * 16 + g;
#pragma unroll
        for (int ni = 0; ni < NI; ni++) {
            const int col = bn + wn + ni * 8 + tg * 2;
            const float2 bv = *(const float2*)(bias + col);
            const float a0 = acc[mi][ni][0] + bv.x;
            const float a1 = acc[mi][ni][1] + bv.y;
            const float a2 = acc[mi][ni][2] + bv.x;
            const float a3 = acc[mi][ni][3] + bv.y;
            if (EPI == 1) {
                if (col < DIM) {     // q -> fp32, stride DIM
                    float2 o0, o1;
                    o0.x = a0; o0.y = a1;
                    o1.x = a2; o1.y = a3;
                    *(float2*)(C + (size_t)r0 * DIM + col) = o0;
                    *(float2*)(C + (size_t)(r0 + 8) * DIM + col) = o1;
                } else {             // k|v -> fp16, stride 1024
                    const int c2 = col - DIM;
                    __half2 o0 = __floats2half2_rn(a0, a1);
                    __half2 o1 = __floats2half2_rn(a2, a3);
                    *(__half2*)(C2 + (size_t)r0 * 1024 + c2) = o0;
                    *(__half2*)(C2 + (size_t)(r0 + 8) * 1024 + c2) = o1;
                }
            } else if (SK == 1) {
                float2 o0, o1;
                o0.x = a0; o0.y = a1;
                o1.x = a2; o1.y = a3;
                *(float2*)(C + (size_t)r0 * N + col) = o0;
                *(float2*)(C + (size_t)(r0 + 8) * N + col) = o1;
            } else {
                const float bx = (kslice == 0) ? 0.f : bv.x;
                const float by = (kslice == 0) ? 0.f : bv.y;
                float* p0 = C + (size_t)r0 * N + col;
                float* p1 = C + (size_t)(r0 + 8) * N + col;
                atomicAdd(p0,     a0 - bx);
                atomicAdd(p0 + 1, a1 - by);
                atomicAdd(p1,     a2 - bx);
                atomicAdd(p1 + 1, a3 - by);
            }
        }
    }
}

#define GEMM_SMEM_96  (2 * (AMATB + 96 * ROWB))    // 35840
#define GEMM_SMEM_128 (2 * (AMATB + 128 * ROWB))   // 40960

// ---------------------------------------------------------------------------
// Neighborhood attention: one warp per (pixel, head). q fp32, k/v fp16.
// Score phase: half-warp per neighbor, uint2 (4 fp16) loads, 4 shfls / 2 nbrs.
// Probs parked in smem; AV via half2 loads. fp16 output.
// ---------------------------------------------------------------------------
__global__ void __launch_bounds__(256) nat_attn(
    const float* __restrict__ q, const __half* __restrict__ kvh,
    const float* __restrict__ rpb,
    __half* __restrict__ ao)
{
    __shared__ float sprob[8][52];

    const int warp = threadIdx.x >> 5;
    const int lane = threadIdx.x & 31;
    const int j = blockIdx.x * 8 + warp;
    const int i = blockIdx.y;
    const int h = blockIdx.z;
    const int pix = i * HWDIM + j;

    const int sh = min(max(i - 3, 0), HWDIM - KWIN);
    const int sw = min(max(j - 3, 0), HWDIM - KWIN);

    const int half_ = lane >> 4;
    const int l15 = lane & 15;

    float4 q4 = ((const float4*)(q + (size_t)pix * DIM + h * HD))[l15];
    q4.x *= 0.125f; q4.y *= 0.125f; q4.z *= 0.125f; q4.w *= 0.125f;

    const float* rp = rpb + h * 169 + (sh - i + 6) * 13 + (sw - j + 6);
    const __half* kb = kvh + (size_t)(sh * HWDIM + sw) * 1024 + h * HD;

#pragma unroll
    for (int it = 0; it < 25; it++) {
        const int t = 2 * it + half_;
        const bool valid = (t < 49);
        const int tt = valid ? t : 0;
        const unsigned a = ((unsigned)tt * 37u) >> 8;
        const int c = tt - 7 * (int)a;
        const uint2 kr = *(const uint2*)(kb + ((size_t)a * HWDIM + c) * 1024 + l15 * 4);
        const float2 f0 = __half22float2(*(const __half2*)&kr.x);
        const float2 f1 = __half22float2(*(const __half2*)&kr.y);
        float s = q4.x * f0.x + q4.y * f0.y + q4.z * f1.x + q4.w * f1.y;
        s += __shfl_xor_sync(0xffffffffu, s, 1);
        s += __shfl_xor_sync(0xffffffffu, s, 2);
        s += __shfl_xor_sync(0xffffffffu, s, 4);
        s += __shfl_xor_sync(0xffffffffu, s, 8);
        if (l15 == 0 && valid)
            sprob[warp][t] = s + rp[a * 13 + c];
    }
    __syncwarp();

    float s0 = sprob[warp][lane];
    float s1 = (lane + 32 < 49) ? sprob[warp][lane + 32] : -1e30f;
    float m = fmaxf(s0, s1);
#pragma unroll
    for (int o = 16; o; o >>= 1)
        m = fmaxf(m, __shfl_xor_sync(0xffffffffu, m, o));
    float e0 = __expf(s0 - m);
    float e1 = (lane + 32 < 49) ? __expf(s1 - m) : 0.f;
    float sum = e0 + e1;
#pragma unroll
    for (int o = 16; o; o >>= 1)
        sum += __shfl_xor_sync(0xffffffffu, sum, o);
    const float inv = __fdividef(1.f, sum);
    sprob[warp][lane] = e0 * inv;
    if (lane + 32 < 49) sprob[warp][lane + 32] = e1 * inv;
    __syncwarp();

    float ax = 0.f, ay = 0.f;
    const __half* vb = kvh + (size_t)(sh * HWDIM + sw) * 1024 + 512 + h * HD;
#pragma unroll
    for (int a = 0; a < KWIN; a++) {
#pragma unroll
        for (int c = 0; c < KWIN; c++) {
            const float at = sprob[warp][a * 7 + c];
            const __half2 vv =
                *(const __half2*)(vb + ((size_t)a * HWDIM + c) * 1024 + 2 * lane);
            const float2 f = __half22float2(vv);
            ax = fmaf(at, f.x, ax);
            ay = fmaf(at, f.y, ay);
        }
    }

    __half2 o = __floats2half2_rn(ax, ay);
    *(__half2*)(ao + (size_t)pix * DIM + h * HD + 2 * lane) = o;
}

// ---------------------------------------------------------------------------
extern "C" void kernel_launch(void* const* d_in, const int* in_sizes, int n_in,
                              void* d_out, int out_size)
{
    const float* x      = (const float*)d_in[0];
    const float* qkv_w  = (const float*)d_in[1];
    const float* qkv_b  = (const float*)d_in[2];
    const float* rpb    = (const float*)d_in[3];
    const float* proj_w = (const float*)d_in[4];
    const float* proj_b = (const float*)d_in[5];
    float* out = (float*)d_out;

    float *q;
    __half *kvh, *xh, *w1h, *ao, *w2h;
    cudaGetSymbolAddress((void**)&q, g_q);
    cudaGetSymbolAddress((void**)&kvh, g_kvh);
    cudaGetSymbolAddress((void**)&xh, g_xh);
    cudaGetSymbolAddress((void**)&w1h, g_w1h);
    cudaGetSymbolAddress((void**)&ao, g_ao);
    cudaGetSymbolAddress((void**)&w2h, g_w2h);

    cudaFuncSetAttribute((const void*)gemm_f16<96, 1, 1>,
                         cudaFuncAttributeMaxDynamicSharedMemorySize, GEMM_SMEM_96);
    cudaFuncSetAttribute((const void*)gemm_f16<128, 2, 0>,
                         cudaFuncAttributeMaxDynamicSharedMemorySize, GEMM_SMEM_128);

    // 0) Zero the split-K target + convert inputs
    zero_out<<<NPIX * DIM / 1024, 256>>>(out);
    cvt_all<<<(N_X + N_W1 + N_W2) / 1024, 256>>>(
        x, qkv_w, proj_w, xh, w1h, w2h);

    // 1) QKV projection: q -> fp32, k|v -> fp16 (split epilogue)
    gemm_f16<96, 1, 1><<<dim3(QKVN / 96, NPIX / 128), 256, GEMM_SMEM_96>>>(
        xh, w1h, qkv_b, q, kvh, NPIX, QKVN, DIM);

    // 2) Neighborhood attention (fp16 k/v; fp16 output)
    nat_attn<<<dim3(HWDIM / 8, HWDIM, NHEAD), 256>>>(q, kvh, rpb, ao);

    // 3) Output projection: 128x128 tiles, split-K=2 (400 CTAs)
    gemm_f16<128, 2, 0><<<dim3(DIM / 128, NPIX / 128, 2), 256, GEMM_SMEM_128>>>(
        ao, w2h, proj_b, out, nullptr, NPIX, DIM, DIM);
}

// round 15
// speedup vs baseline: 1.9419x; 1.1013x over previous
#include <cuda_runtime.h>
#include <cuda_bf16.h>
#include <cuda_fp16.h>
#include <cstdint>
#include <math.h>

// Problem constants
#define HWDIM 80
#define NPIX  6400
#define DIM   512
#define QKVN  1536
#define NHEAD 8
#define HD    64
#define KWIN  7

// Scratch (allocation-free rule: __device__ globals)
__device__ float g_q[(size_t)NPIX * DIM];          // q fp32
__device__ __half g_kvh[(size_t)NPIX * 1024];      // k|v fp16
__device__ __half g_xh[(size_t)NPIX * DIM];        // x fp16
__device__ __half g_w1h[(size_t)QKVN * DIM];       // qkv_w fp16
__device__ __half g_ao[(size_t)NPIX * DIM];        // attn out fp16
__device__ __half g_w2h[(size_t)DIM * DIM];        // proj_w fp16

#define N_X  (NPIX * DIM)
#define N_W1 (QKVN * DIM)
#define N_W2 (DIM * DIM)

__device__ __forceinline__ uint32_t smem_u32(const void* p) {
    uint32_t a;
    asm("{ .reg .u64 t; cvta.to.shared.u64 t, %1; cvt.u32.u64 %0, t; }"
        : "=r"(a) : "l"(p));
    return a;
}
__device__ __forceinline__ void cp16(uint32_t dst, const void* src) {
    asm volatile("cp.async.cg.shared.global [%0], [%1], 16;"
                 :: "r"(dst), "l"(src));
}
__device__ __forceinline__ void cp_commit() {
    asm volatile("cp.async.commit_group;" ::: "memory");
}
__device__ __forceinline__ void cp_wait0() {
    asm volatile("cp.async.wait_group 0;" ::: "memory");
}

// ---------------------------------------------------------------------------
// Zero-init for the split-K accumulation target.
// ---------------------------------------------------------------------------
__global__ void __launch_bounds__(256) zero_out(float* __restrict__ p)
{
    const int i = (blockIdx.x * 256 + threadIdx.x) * 4;
    float4 z; z.x = 0.f; z.y = 0.f; z.z = 0.f; z.w = 0.f;
    *(float4*)(p + i) = z;
}

// ---------------------------------------------------------------------------
// Convert inputs: x, qkv_w, proj_w -> plain fp16. One launch.
// ---------------------------------------------------------------------------
__global__ void __launch_bounds__(256) cvt_all(
    const float* __restrict__ x, const float* __restrict__ w1,
    const float* __restrict__ w2,
    __half* __restrict__ xh, __half* __restrict__ w1h,
    __half* __restrict__ w2h)
{
    int i = (blockIdx.x * 256 + threadIdx.x) * 4;
    const float* src;
    __half* dst;
    if (i < N_X)              { src = x + i;             dst = xh + i; }
    else if (i < N_X + N_W1)  { i -= N_X;  src = w1 + i; dst = w1h + i; }
    else                      { i -= N_X + N_W1; src = w2 + i; dst = w2h + i; }

    float4 v = *(const float4*)src;
    __half2 h0 = __floats2half2_rn(v.x, v.y);
    __half2 h1 = __floats2half2_rn(v.z, v.w);
    uint2 o; o.x = *(uint32_t*)&h0; o.y = *(uint32_t*)&h1;
    *(uint2*)dst = o;
}

// ---------------------------------------------------------------------------
// mma.sync fp16 GEMM: C = A @ B^T + bias  (plain fp16 A and B, fp32 accum)
// 128 x BN CTA tile, 256 threads = 8 warps in 2(m) x 4(n); warp 64 x (BN/4).
// EPI=0: fp32 C (SK-way split-K via atomics when SK>1).
// EPI=1: QKV split epilogue — cols [0,512) fp32 -> C (stride 512),
//                             cols [512,1536) fp16 -> C2 (stride 1024).
// ---------------------------------------------------------------------------
#define BK 32
#define ROWB 80
#define AMATB (128 * ROWB)

__device__ __forceinline__ void ldmx4(uint32_t* r, uint32_t addr) {
    asm volatile("ldmatrix.sync.aligned.m8n8.x4.shared.b16 {%0,%1,%2,%3}, [%4];"
                 : "=r"(r[0]), "=r"(r[1]), "=r"(r[2]), "=r"(r[3]) : "r"(addr));
}
__device__ __forceinline__ void ldmx2(uint32_t* r, uint32_t addr) {
    asm volatile("ldmatrix.sync.aligned.m8n8.x2.shared.b16 {%0,%1}, [%2];"
                 : "=r"(r[0]), "=r"(r[1]) : "r"(addr));
}
__device__ __forceinline__ void mma_f16(float* c, const uint32_t* a, const uint32_t* b) {
    asm volatile(
        "mma.sync.aligned.m16n8k16.row.col.f32.f16.f16.f32 "
        "{%0,%1,%2,%3}, {%4,%5,%6,%7}, {%8,%9}, {%0,%1,%2,%3};"
        : "+f"(c[0]), "+f"(c[1]), "+f"(c[2]), "+f"(c[3])
        : "r"(a[0]), "r"(a[1]), "r"(a[2]), "r"(a[3]), "r"(b[0]), "r"(b[1]));
}

template<int BN, int SK, int EPI>
__global__ void __launch_bounds__(256, 2) gemm_f16(
    const __half* __restrict__ A, const __half* __restrict__ B,
    const float* __restrict__ bias, float* __restrict__ C,
    __half* __restrict__ C2,
    int M, int N, int K)
{
    constexpr int NI = BN / 32;
    constexpr int BMB = BN * ROWB;
    constexpr int STAGE = AMATB + BMB;
    constexpr int NCH16 = (128 + BN) * 4;        // 16B chunks per stage
    constexpr int NT4 = (NCH16 + 255) / 256;     // cp16 iters per thread

    extern __shared__ char smem[];
    const uint32_t sb = smem_u32(smem);
    const int tid = threadIdx.x;
    const int wid = tid >> 5;
    const int lane = tid & 31;
    const int bm = blockIdx.y * 128;
    const int bn = blockIdx.x * BN;
    const int wm = (wid & 1) * 64;
    const int wn = (wid >> 1) * (BN / 4);
    const int kslice = (SK > 1) ? blockIdx.z : 0;
    const int Keff = K / SK;
    const int kbase = kslice * Keff;

    const __half* gA = A + (size_t)bm * K + kbase;
    const __half* gB = B + (size_t)bn * K + kbase;

    float acc[4][NI][4];
#pragma unroll
    for (int mi = 0; mi < 4; mi++)
#pragma unroll
        for (int ni = 0; ni < NI; ni++)
#pragma unroll
            for (int e = 0; e < 4; e++) acc[mi][ni][e] = 0.f;

    const int nch = Keff / BK;

    auto load_stage = [&](int buf, int k0) {
        const uint32_t st = sb + buf * STAGE;
#pragma unroll
        for (int it = 0; it < NT4; it++) {
            const int f = tid + it * 256;
            if (NCH16 % 256 != 0 && f >= NCH16) break;
            const int r = f >> 2;
            const int c = f & 3;
            const __half* src;
            uint32_t dst;
            if (r < 128) { src = gA + (size_t)r * K;
                           dst = st + r * ROWB; }
            else         { src = gB + (size_t)(r - 128) * K;
                           dst = st + AMATB + (r - 128) * ROWB; }
            cp16(dst + c * 16, src + k0 + c * 8);
        }
    };

    const int a_r  = wm + (lane & 15);
    const int a_k  = (lane >> 4) * 8;
    const int b_nr = (lane & 7) + ((lane >> 4) & 1) * 8;
    const int b_k  = ((lane >> 3) & 1) * 8;

    load_stage(0, 0);
    cp_commit();

    for (int ch = 0; ch < nch; ch++) {
        cp_wait0();
        __syncthreads();
        if (ch + 1 < nch) {
            load_stage((ch + 1) & 1, (ch + 1) * BK);
            cp_commit();
        }

        const uint32_t st = sb + (ch & 1) * STAGE;
#pragma unroll
        for (int kk = 0; kk < 2; kk++) {
            uint32_t bf[NI][2];
            const uint32_t bb = st + AMATB + (uint32_t)((kk * 16 + b_k) * 2);
#pragma unroll
            for (int p = 0; p < NI / 2; p++) {
                uint32_t rr[4];
                ldmx4(rr, bb + (wn + p * 16 + b_nr) * ROWB);
                bf[2 * p][0] = rr[0]; bf[2 * p][1] = rr[1];
                bf[2 * p + 1][0] = rr[2]; bf[2 * p + 1][1] = rr[3];
            }
            if (NI & 1) {
                const uint32_t addr = st + AMATB
                    + (uint32_t)((wn + (NI - 1) * 8 + (lane & 7)) * ROWB
                                 + (kk * 16 + b_k) * 2);
                ldmx2(bf[NI - 1], addr);
            }
            const uint32_t ab = st + (uint32_t)(a_r * ROWB + (kk * 16 + a_k) * 2);
#pragma unroll
            for (int mi = 0; mi < 4; mi++) {
                uint32_t af[4];
                ldmx4(af, ab + mi * 16 * ROWB);
#pragma unroll
                for (int ni = 0; ni < NI; ni++)
                    mma_f16(acc[mi][ni], af, bf[ni]);
            }
        }
    }

    const int g = lane >> 2;
    const int tg = lane & 3;
#pragma unroll
    for (int mi = 0; mi < 4; mi++) {
        const int r0 = bm + wm + mi * 16 + g;
#pragma unroll
        for (int ni = 0; ni < NI; ni++) {
            const int col = bn + wn + ni * 8 + tg * 2;
            const float2 bv = *(const float2*)(bias + col);
            const float a0 = acc[mi][ni][0] + bv.x;
            const float a1 = acc[mi][ni][1] + bv.y;
            const float a2 = acc[mi][ni][2] + bv.x;
            const float a3 = acc[mi][ni][3] + bv.y;
            if (EPI == 1) {
                if (col < DIM) {     // q -> fp32, stride DIM
                    float2 o0, o1;
                    o0.x = a0; o0.y = a1;
                    o1.x = a2; o1.y = a3;
                    *(float2*)(C + (size_t)r0 * DIM + col) = o0;
                    *(float2*)(C + (size_t)(r0 + 8) * DIM + col) = o1;
                } else {             // k|v -> fp16, stride 1024
                    const int c2 = col - DIM;
                    __half2 o0 = __floats2half2_rn(a0, a1);
                    __half2 o1 = __floats2half2_rn(a2, a3);
                    *(__half2*)(C2 + (size_t)r0 * 1024 + c2) = o0;
                    *(__half2*)(C2 + (size_t)(r0 + 8) * 1024 + c2) = o1;
                }
            } else if (SK == 1) {
                float2 o0, o1;
                o0.x = a0; o0.y = a1;
                o1.x = a2; o1.y = a3;
                *(float2*)(C + (size_t)r0 * N + col) = o0;
                *(float2*)(C + (size_t)(r0 + 8) * N + col) = o1;
            } else {
                const float bx = (kslice == 0) ? 0.f : bv.x;
                const float by = (kslice == 0) ? 0.f : bv.y;
                float* p0 = C + (size_t)r0 * N + col;
                float* p1 = C + (size_t)(r0 + 8) * N + col;
                atomicAdd(p0,     a0 - bx);
                atomicAdd(p0 + 1, a1 - by);
                atomicAdd(p1,     a2 - bx);
                atomicAdd(p1 + 1, a3 - by);
            }
        }
    }
}

#define GEMM_SMEM_96  (2 * (AMATB + 96 * ROWB))    // 35840
#define GEMM_SMEM_128 (2 * (AMATB + 128 * ROWB))   // 40960

// ---------------------------------------------------------------------------
// Neighborhood attention: one warp per (pixel, head). q fp32, k/v fp16.
// Score phase: QUARTER-warp per neighbor — lane owns 8 dims (uint4 k load),
// 4 neighbors per iteration, 3-shfl reduction over 8 lanes.
// Probs parked in smem; AV via half2 loads. fp16 output.
// ---------------------------------------------------------------------------
__global__ void __launch_bounds__(256) nat_attn(
    const float* __restrict__ q, const __half* __restrict__ kvh,
    const float* __restrict__ rpb,
    __half* __restrict__ ao)
{
    __shared__ float sprob[8][52];

    const int warp = threadIdx.x >> 5;
    const int lane = threadIdx.x & 31;
    const int j = blockIdx.x * 8 + warp;
    const int i = blockIdx.y;
    const int h = blockIdx.z;
    const int pix = i * HWDIM + j;

    const int sh = min(max(i - 3, 0), HWDIM - KWIN);
    const int sw = min(max(j - 3, 0), HWDIM - KWIN);

    const int quarter = lane >> 3;   // 0..3: neighbor within iteration group
    const int l8 = lane & 7;         // dim-octet owner

    // q: 8 dims per lane (scaled)
    float qf[8];
    {
        const float* qp = q + (size_t)pix * DIM + h * HD + l8 * 8;
        const float4 qa = *(const float4*)qp;
        const float4 qb = *(const float4*)(qp + 4);
        qf[0] = qa.x * 0.125f; qf[1] = qa.y * 0.125f;
        qf[2] = qa.z * 0.125f; qf[3] = qa.w * 0.125f;
        qf[4] = qb.x * 0.125f; qf[5] = qb.y * 0.125f;
        qf[6] = qb.z * 0.125f; qf[7] = qb.w * 0.125f;
    }

    const float* rp = rpb + h * 169 + (sh - i + 6) * 13 + (sw - j + 6);
    const __half* kb = kvh + (size_t)(sh * HWDIM + sw) * 1024 + h * HD;

    // --- scores: 4 neighbors per iteration (one per quarter-warp) ---
#pragma unroll
    for (int it = 0; it < 13; it++) {
        const int t = 4 * it + quarter;
        const bool valid = (t < 49);
        const int tt = valid ? t : 0;
        const unsigned a = ((unsigned)tt * 37u) >> 8;    // tt / 7
        const int c = tt - 7 * (int)a;
        const uint4 kr = *(const uint4*)(kb + ((size_t)a * HWDIM + c) * 1024 + l8 * 8);
        const float2 f0 = __half22float2(*(const __half2*)&kr.x);
        const float2 f1 = __half22float2(*(const __half2*)&kr.y);
        const float2 f2 = __half22float2(*(const __half2*)&kr.z);
        const float2 f3 = __half22float2(*(const __half2*)&kr.w);
        float s = qf[0] * f0.x + qf[1] * f0.y + qf[2] * f1.x + qf[3] * f1.y
                + qf[4] * f2.x + qf[5] * f2.y + qf[6] * f3.x + qf[7] * f3.y;
        s += __shfl_xor_sync(0xffffffffu, s, 1);
        s += __shfl_xor_sync(0xffffffffu, s, 2);
        s += __shfl_xor_sync(0xffffffffu, s, 4);
        if (l8 == 0 && valid)
            sprob[warp][t] = s + rp[a * 13 + c];
    }
    __syncwarp();

    // --- softmax over 49 scores ---
    float s0 = sprob[warp][lane];
    float s1 = (lane + 32 < 49) ? sprob[warp][lane + 32] : -1e30f;
    float m = fmaxf(s0, s1);
#pragma unroll
    for (int o = 16; o; o >>= 1)
        m = fmaxf(m, __shfl_xor_sync(0xffffffffu, m, o));
    float e0 = __expf(s0 - m);
    float e1 = (lane + 32 < 49) ? __expf(s1 - m) : 0.f;
    float sum = e0 + e1;
#pragma unroll
    for (int o = 16; o; o >>= 1)
        sum += __shfl_xor_sync(0xffffffffu, sum, o);
    const float inv = __fdividef(1.f, sum);
    sprob[warp][lane] = e0 * inv;
    if (lane + 32 < 49) sprob[warp][lane + 32] = e1 * inv;
    __syncwarp();

    // --- AV: lane owns dims 2*lane, 2*lane+1 ---
    float ax = 0.f, ay = 0.f;
    const __half* vb = kvh + (size_t)(sh * HWDIM + sw) * 1024 + 512 + h * HD;
#pragma unroll
    for (int a = 0; a < KWIN; a++) {
#pragma unroll
        for (int c = 0; c < KWIN; c++) {
            const float at = sprob[warp][a * 7 + c];
            const __half2 vv =
                *(const __half2*)(vb + ((size_t)a * HWDIM + c) * 1024 + 2 * lane);
            const float2 f = __half22float2(vv);
            ax = fmaf(at, f.x, ax);
            ay = fmaf(at, f.y, ay);
        }
    }

    __half2 o = __floats2half2_rn(ax, ay);
    *(__half2*)(ao + (size_t)pix * DIM + h * HD + 2 * lane) = o;
}

// ---------------------------------------------------------------------------
extern "C" void kernel_launch(void* const* d_in, const int* in_sizes, int n_in,
                              void* d_out, int out_size)
{
    const float* x      = (const float*)d_in[0];
    const float* qkv_w  = (const float*)d_in[1];
    const float* qkv_b  = (const float*)d_in[2];
    const float* rpb    = (const float*)d_in[3];
    const float* proj_w = (const float*)d_in[4];
    const float* proj_b = (const float*)d_in[5];
    float* out = (float*)d_out;

    float *q;
    __half *kvh, *xh, *w1h, *ao, *w2h;
    cudaGetSymbolAddress((void**)&q, g_q);
    cudaGetSymbolAddress((void**)&kvh, g_kvh);
    cudaGetSymbolAddress((void**)&xh, g_xh);
    cudaGetSymbolAddress((void**)&w1h, g_w1h);
    cudaGetSymbolAddress((void**)&ao, g_ao);
    cudaGetSymbolAddress((void**)&w2h, g_w2h);

    cudaFuncSetAttribute((const void*)gemm_f16<96, 1, 1>,
                         cudaFuncAttributeMaxDynamicSharedMemorySize, GEMM_SMEM_96);
    cudaFuncSetAttribute((const void*)gemm_f16<128, 2, 0>,
                         cudaFuncAttributeMaxDynamicSharedMemorySize, GEMM_SMEM_128);

    // 0) Zero the split-K target + convert inputs
    zero_out<<<NPIX * DIM / 1024, 256>>>(out);
    cvt_all<<<(N_X + N_W1 + N_W2) / 1024, 256>>>(
        x, qkv_w, proj_w, xh, w1h, w2h);

    // 1) QKV projection: q -> fp32, k|v -> fp16 (split epilogue)
    gemm_f16<96, 1, 1><<<dim3(QKVN / 96, NPIX / 128), 256, GEMM_SMEM_96>>>(
        xh, w1h, qkv_b, q, kvh, NPIX, QKVN, DIM);

    // 2) Neighborhood attention (fp16 k/v; fp16 output)
    nat_attn<<<dim3(HWDIM / 8, HWDIM, NHEAD), 256>>>(q, kvh, rpb, ao);

    // 3) Output projection: 128x128 tiles, split-K=2 (400 CTAs)
    gemm_f16<128, 2, 0><<<dim3(DIM / 128, NPIX / 128, 2), 256, GEMM_SMEM_128>>>(
        ao, w2h, proj_b, out, nullptr, NPIX, DIM, DIM);
}

// round 16
// speedup vs baseline: 2.1366x; 1.1003x over previous
#include <cuda_runtime.h>
#include <cuda_bf16.h>
#include <cuda_fp16.h>
#include <cstdint>
#include <math.h>

// Problem constants
#define HWDIM 80
#define NPIX  6400
#define DIM   512
#define QKVN  1536
#define NHEAD 8
#define HD    64
#define KWIN  7

// Scratch (allocation-free rule: __device__ globals)
__device__ __half g_qh[(size_t)NPIX * DIM];        // q fp16 (pre-scaled 1/8)
__device__ __half g_kvh[(size_t)NPIX * 1024];      // k|v fp16
__device__ __half g_xh[(size_t)NPIX * DIM];        // x fp16
__device__ __half g_w1h[(size_t)QKVN * DIM];       // qkv_w fp16
__device__ __half g_ao[(size_t)NPIX * DIM];        // attn out fp16
__device__ __half g_w2h[(size_t)DIM * DIM];        // proj_w fp16

#define N_X  (NPIX * DIM)
#define N_W1 (QKVN * DIM)
#define N_W2 (DIM * DIM)

__device__ __forceinline__ uint32_t smem_u32(const void* p) {
    uint32_t a;
    asm("{ .reg .u64 t; cvta.to.shared.u64 t, %1; cvt.u32.u64 %0, t; }"
        : "=r"(a) : "l"(p));
    return a;
}
__device__ __forceinline__ void cp16(uint32_t dst, const void* src) {
    asm volatile("cp.async.cg.shared.global [%0], [%1], 16;"
                 :: "r"(dst), "l"(src));
}
__device__ __forceinline__ void cp_commit() {
    asm volatile("cp.async.commit_group;" ::: "memory");
}
__device__ __forceinline__ void cp_wait0() {
    asm volatile("cp.async.wait_group 0;" ::: "memory");
}
__device__ __forceinline__ void ldmx4(uint32_t* r, uint32_t addr) {
    asm volatile("ldmatrix.sync.aligned.m8n8.x4.shared.b16 {%0,%1,%2,%3}, [%4];"
                 : "=r"(r[0]), "=r"(r[1]), "=r"(r[2]), "=r"(r[3]) : "r"(addr));
}
__device__ __forceinline__ void ldmx2(uint32_t* r, uint32_t addr) {
    asm volatile("ldmatrix.sync.aligned.m8n8.x2.shared.b16 {%0,%1}, [%2];"
                 : "=r"(r[0]), "=r"(r[1]) : "r"(addr));
}
__device__ __forceinline__ void ldmx2t(uint32_t* r, uint32_t addr) {
    asm volatile("ldmatrix.sync.aligned.m8n8.x2.trans.shared.b16 {%0,%1}, [%2];"
                 : "=r"(r[0]), "=r"(r[1]) : "r"(addr));
}
__device__ __forceinline__ void mma_f16(float* c, const uint32_t* a, const uint32_t* b) {
    asm volatile(
        "mma.sync.aligned.m16n8k16.row.col.f32.f16.f16.f32 "
        "{%0,%1,%2,%3}, {%4,%5,%6,%7}, {%8,%9}, {%0,%1,%2,%3};"
        : "+f"(c[0]), "+f"(c[1]), "+f"(c[2]), "+f"(c[3])
        : "r"(a[0]), "r"(a[1]), "r"(a[2]), "r"(a[3]), "r"(b[0]), "r"(b[1]));
}

// ---------------------------------------------------------------------------
// Zero-init for the split-K accumulation target.
// ---------------------------------------------------------------------------
__global__ void __launch_bounds__(256) zero_out(float* __restrict__ p)
{
    const int i = (blockIdx.x * 256 + threadIdx.x) * 4;
    float4 z; z.x = 0.f; z.y = 0.f; z.z = 0.f; z.w = 0.f;
    *(float4*)(p + i) = z;
}

// ---------------------------------------------------------------------------
// Convert inputs: x, qkv_w, proj_w -> plain fp16. One launch.
// ---------------------------------------------------------------------------
__global__ void __launch_bounds__(256) cvt_all(
    const float* __restrict__ x, const float* __restrict__ w1,
    const float* __restrict__ w2,
    __half* __restrict__ xh, __half* __restrict__ w1h,
    __half* __restrict__ w2h)
{
    int i = (blockIdx.x * 256 + threadIdx.x) * 4;
    const float* src;
    __half* dst;
    if (i < N_X)              { src = x + i;             dst = xh + i; }
    else if (i < N_X + N_W1)  { i -= N_X;  src = w1 + i; dst = w1h + i; }
    else                      { i -= N_X + N_W1; src = w2 + i; dst = w2h + i; }

    float4 v = *(const float4*)src;
    __half2 h0 = __floats2half2_rn(v.x, v.y);
    __half2 h1 = __floats2half2_rn(v.z, v.w);
    uint2 o; o.x = *(uint32_t*)&h0; o.y = *(uint32_t*)&h1;
    *(uint2*)dst = o;
}

// ---------------------------------------------------------------------------
// mma.sync fp16 GEMM: C = A @ B^T + bias  (plain fp16 A and B, fp32 accum)
// EPI=0: fp32 C (SK-way split-K via atomics when SK>1).
// EPI=1: QKV split epilogue — cols [0,512)  -> Cq fp16, scaled 1/8 (q),
//                             cols [512,1536) -> C2 fp16 stride 1024 (k|v).
// ---------------------------------------------------------------------------
#define BK 32
#define ROWB 80
#define AMATB (128 * ROWB)

template<int BN, int SK, int EPI>
__global__ void __launch_bounds__(256, 2) gemm_f16(
    const __half* __restrict__ A, const __half* __restrict__ B,
    const float* __restrict__ bias, float* __restrict__ C,
    __half* __restrict__ C2, __half* __restrict__ Cq,
    int M, int N, int K)
{
    constexpr int NI = BN / 32;
    constexpr int BMB = BN * ROWB;
    constexpr int STAGE = AMATB + BMB;
    constexpr int NCH16 = (128 + BN) * 4;
    constexpr int NT4 = (NCH16 + 255) / 256;

    extern __shared__ char smem[];
    const uint32_t sb = smem_u32(smem);
    const int tid = threadIdx.x;
    const int wid = tid >> 5;
    const int lane = tid & 31;
    const int bm = blockIdx.y * 128;
    const int bn = blockIdx.x * BN;
    const int wm = (wid & 1) * 64;
    const int wn = (wid >> 1) * (BN / 4);
    const int kslice = (SK > 1) ? blockIdx.z : 0;
    const int Keff = K / SK;
    const int kbase = kslice * Keff;

    const __half* gA = A + (size_t)bm * K + kbase;
    const __half* gB = B + (size_t)bn * K + kbase;

    float acc[4][NI][4];
#pragma unroll
    for (int mi = 0; mi < 4; mi++)
#pragma unroll
        for (int ni = 0; ni < NI; ni++)
#pragma unroll
            for (int e = 0; e < 4; e++) acc[mi][ni][e] = 0.f;

    const int nch = Keff / BK;

    auto load_stage = [&](int buf, int k0) {
        const uint32_t st = sb + buf * STAGE;
#pragma unroll
        for (int it = 0; it < NT4; it++) {
            const int f = tid + it * 256;
            if (NCH16 % 256 != 0 && f >= NCH16) break;
            const int r = f >> 2;
            const int c = f & 3;
            const __half* src;
            uint32_t dst;
            if (r < 128) { src = gA + (size_t)r * K;
                           dst = st + r * ROWB; }
            else         { src = gB + (size_t)(r - 128) * K;
                           dst = st + AMATB + (r - 128) * ROWB; }
            cp16(dst + c * 16, src + k0 + c * 8);
        }
    };

    const int a_r  = wm + (lane & 15);
    const int a_k  = (lane >> 4) * 8;
    const int b_nr = (lane & 7) + ((lane >> 4) & 1) * 8;
    const int b_k  = ((lane >> 3) & 1) * 8;

    load_stage(0, 0);
    cp_commit();

    for (int ch = 0; ch < nch; ch++) {
        cp_wait0();
        __syncthreads();
        if (ch + 1 < nch) {
            load_stage((ch + 1) & 1, (ch + 1) * BK);
            cp_commit();
        }

        const uint32_t st = sb + (ch & 1) * STAGE;
#pragma unroll
        for (int kk = 0; kk < 2; kk++) {
            uint32_t bf[NI][2];
            const uint32_t bb = st + AMATB + (uint32_t)((kk * 16 + b_k) * 2);
#pragma unroll
            for (int p = 0; p < NI / 2; p++) {
                uint32_t rr[4];
                ldmx4(rr, bb + (wn + p * 16 + b_nr) * ROWB);
                bf[2 * p][0] = rr[0]; bf[2 * p][1] = rr[1];
                bf[2 * p + 1][0] = rr[2]; bf[2 * p + 1][1] = rr[3];
            }
            if (NI & 1) {
                const uint32_t addr = st + AMATB
                    + (uint32_t)((wn + (NI - 1) * 8 + (lane & 7)) * ROWB
                                 + (kk * 16 + b_k) * 2);
                ldmx2(bf[NI - 1], addr);
            }
            const uint32_t ab = st + (uint32_t)(a_r * ROWB + (kk * 16 + a_k) * 2);
#pragma unroll
            for (int mi = 0; mi < 4; mi++) {
                uint32_t af[4];
                ldmx4(af, ab + mi * 16 * ROWB);
#pragma unroll
                for (int ni = 0; ni < NI; ni++)
                    mma_f16(acc[mi][ni], af, bf[ni]);
            }
        }
    }

    const int g = lane >> 2;
    const int tg = lane & 3;
#pragma unroll
    for (int mi = 0; mi < 4; mi++) {
        const int r0 = bm + wm + mi * 16 + g;
#pragma unroll
        for (int ni = 0; ni < NI; ni++) {
            const int col = bn + wn + ni * 8 + tg * 2;
            const float2 bv = *(const float2*)(bias + col);
            const float a0 = acc[mi][ni][0] + bv.x;
            const float a1 = acc[mi][ni][1] + bv.y;
            const float a2 = acc[mi][ni][2] + bv.x;
            const float a3 = acc[mi][ni][3] + bv.y;
            if (EPI == 1) {
                if (col < DIM) {     // q -> fp16 scaled, stride DIM
                    __half2 o0 = __floats2half2_rn(a0 * 0.125f, a1 * 0.125f);
                    __half2 o1 = __floats2half2_rn(a2 * 0.125f, a3 * 0.125f);
                    *(__half2*)(Cq + (size_t)r0 * DIM + col) = o0;
                    *(__half2*)(Cq + (size_t)(r0 + 8) * DIM + col) = o1;
                } else {             // k|v -> fp16, stride 1024
                    const int c2 = col - DIM;
                    __half2 o0 = __floats2half2_rn(a0, a1);
                    __half2 o1 = __floats2half2_rn(a2, a3);
                    *(__half2*)(C2 + (size_t)r0 * 1024 + c2) = o0;
                    *(__half2*)(C2 + (size_t)(r0 + 8) * 1024 + c2) = o1;
                }
            } else if (SK == 1) {
                float2 o0, o1;
                o0.x = a0; o0.y = a1;
                o1.x = a2; o1.y = a3;
                *(float2*)(C + (size_t)r0 * N + col) = o0;
                *(float2*)(C + (size_t)(r0 + 8) * N + col) = o1;
            } else {
                const float bx = (kslice == 0) ? 0.f : bv.x;
                const float by = (kslice == 0) ? 0.f : bv.y;
                float* p0 = C + (size_t)r0 * N + col;
                float* p1 = C + (size_t)(r0 + 8) * N + col;
                atomicAdd(p0,     a0 - bx);
                atomicAdd(p0 + 1, a1 - by);
                atomicAdd(p1,     a2 - bx);
                atomicAdd(p1 + 1, a3 - by);
            }
        }
    }
}

#define GEMM_SMEM_96  (2 * (AMATB + 96 * ROWB))
#define GEMM_SMEM_128 (2 * (AMATB + 128 * ROWB))

// ---------------------------------------------------------------------------
// Neighborhood attention via tensor cores.
// Block = 16 pixels (one row i) x 1 head; grid (5, 80, 8); 256 threads.
// Union window: 7 x wb (wb<=22) neighbors, padded to 160 cols (layout a*22+c).
// k/v staged in smem (fp16, 144B row stride); q fp16 pre-scaled.
// QK^T: 12/8 MMAs per warp -> scores smem -> bias+mask+softmax (16 teams)
// -> fp16 probs -> AV: probs x v^T (ldmatrix.trans), 10 MMAs per warp.
// ---------------------------------------------------------------------------
#define NU 160
#define KVROW 144
#define OFF_K  0
#define OFF_V  (NU * KVROW)                  // 23040
#define OFF_Q  (2 * NU * KVROW)              // 46080
#define OFF_P  (OFF_Q + 16 * KVROW)          // 48384  probs 16 x 336B
#define OFF_S  (OFF_P + 16 * 336)            // 53760  scores 16 x 160 fp32
#define OFF_RO (OFF_S + 16 * NU * 4)         // 64000  row offsets (160 u32)
#define OFF_AC (OFF_RO + NU * 4)             // 64640  (a,c) LUT (160 u32)
#define ATTN_SMEM (OFF_AC + NU * 4)          // 65280

__global__ void __launch_bounds__(256) nat_attn_mma(
    const __half* __restrict__ qh, const __half* __restrict__ kvh,
    const float* __restrict__ rpb,
    __half* __restrict__ ao)
{
    extern __shared__ char smA[];
    const uint32_t sb = smem_u32(smA);

    const int tid = threadIdx.x;
    const int warp = tid >> 5;
    const int lane = tid & 31;
    const int jb = blockIdx.x * 16;
    const int i = blockIdx.y;
    const int h = blockIdx.z;

    const int sh = min(max(i - 3, 0), HWDIM - KWIN);
    const int cmin = min(max(jb - 3, 0), HWDIM - KWIN);
    const int cmax = min(max(jb + 12, 0), HWDIM - KWIN) + 6;
    const int wb = cmax - cmin + 1;            // 19..22
    const int dh0 = sh - i + 6;

    // --- tables: per-union-column gmem row offset (clamped) + (a,c) LUT ---
    uint32_t* RO = (uint32_t*)(smA + OFF_RO);
    uint32_t* AC = (uint32_t*)(smA + OFF_AC);
    if (tid < NU) {
        const int s = tid;
        int a = (s * 2979) >> 16;              // s / 22
        const int c = s - 22 * a;
        AC[s] = (uint32_t)(a * 32 + c);        // unclamped for masking
        if (a > 6) a = 6;                      // clamp pad rows to valid data
        const int ccl = min(c, wb - 1);
        RO[s] = (uint32_t)(((sh + a) * HWDIM + cmin + ccl) * 1024 + h * HD);
    }
    __syncthreads();

    // --- stage k/v (160 rows x 64 fp16 each) and q (16 rows) via cp.async ---
#pragma unroll
    for (int it = 0; it < 10; it++) {
        const int idx = tid + it * 256;        // 0..2559
        const int row = idx >> 4;
        const int part = idx & 15;
        const int kv = part >> 3;
        const int ch = part & 7;
        const uint32_t go = RO[row] + kv * 512 + ch * 8;
        const uint32_t dst = sb + (kv ? OFF_V : OFF_K) + row * KVROW + ch * 16;
        cp16(dst, kvh + go);
    }
    if (tid < 128) {
        const int r = tid >> 3, ch = tid & 7;
        cp16(sb + OFF_Q + r * KVROW + ch * 16,
             qh + (size_t)(i * HWDIM + jb + r) * DIM + h * HD + ch * 8);
    }
    cp_commit();
    cp_wait0();
    __syncthreads();

    // --- QK^T: warp w covers n-cols [16w,16w+16) + (w<4: [128+8w, +8)) ---
    const int g = lane >> 2;
    const int tg = lane & 3;
    const int a_r = lane & 15;
    const int a_k = (lane >> 4) * 8;
    const int b_nr = (lane & 7) + ((lane >> 4) & 1) * 8;
    const int b_k = ((lane >> 3) & 1) * 8;

    {
        float accP[2][4] = {{0.f}}, accE[4] = {0.f};
#pragma unroll
        for (int kk = 0; kk < 4; kk++) {
            uint32_t af[4];
            ldmx4(af, sb + OFF_Q + a_r * KVROW + (kk * 16 + a_k) * 2);
            uint32_t bp[4];
            ldmx4(bp, sb + OFF_K + (16 * warp + b_nr) * KVROW + (kk * 16 + b_k) * 2);
            uint32_t b0[2] = {bp[0], bp[1]}, b1[2] = {bp[2], bp[3]};
            mma_f16(accP[0], af, b0);
            mma_f16(accP[1], af, b1);
            if (warp < 4) {
                uint32_t be[2];
                ldmx2(be, sb + OFF_K + (128 + 8 * warp + (lane & 7)) * KVROW
                          + (kk * 16 + b_k) * 2);
                mma_f16(accE, af, be);
            }
        }
        float* S = (float*)(smA + OFF_S);
#pragma unroll
        for (int ni = 0; ni < 2; ni++) {
            const int cb = 16 * warp + ni * 8 + tg * 2;
            float2 t0; t0.x = accP[ni][0]; t0.y = accP[ni][1];
            float2 t1; t1.x = accP[ni][2]; t1.y = accP[ni][3];
            *(float2*)&S[g * NU + cb] = t0;
            *(float2*)&S[(g + 8) * NU + cb] = t1;
        }
        if (warp < 4) {
            const int cb = 128 + 8 * warp + tg * 2;
            float2 t0; t0.x = accE[0]; t0.y = accE[1];
            float2 t1; t1.x = accE[2]; t1.y = accE[3];
            *(float2*)&S[g * NU + cb] = t0;
            *(float2*)&S[(g + 8) * NU + cb] = t1;
        }
    }
    __syncthreads();

    // --- bias + mask + softmax: 16 teams of 16 lanes (one pixel each) ---
    {
        const int p = tid >> 4;
        const int l16 = tid & 15;
        const int jp = jb + p;
        const int swp = min(max(jp - 3, 0), HWDIM - KWIN);
        const float* S = (const float*)(smA + OFF_S);
        const float* rpbase = rpb + h * 169 + dh0 * 13;
        float vals[10];
        float mx = -1e30f;
#pragma unroll
        for (int u = 0; u < 10; u++) {
            const int col = l16 + u * 16;
            const uint32_t ac = AC[col];
            const int a = ac >> 5;
            const int c = ac & 31;
            const int cw = cmin + c;
            const int d = cw - swp;
            const bool ok = (a < 7) && (c < wb) && (d >= 0) && (d <= 6);
            float s = -1e30f;
            if (ok) s = S[p * NU + col] + rpbase[a * 13 + (cw - jp + 6)];
            vals[u] = s;
            mx = fmaxf(mx, s);
        }
#pragma unroll
        for (int o = 8; o; o >>= 1)
            mx = fmaxf(mx, __shfl_xor_sync(0xffffffffu, mx, o));
        float sum = 0.f;
#pragma unroll
        for (int u = 0; u < 10; u++) {
            vals[u] = __expf(vals[u] - mx);
            sum += vals[u];
        }
#pragma unroll
        for (int o = 8; o; o >>= 1)
            sum += __shfl_xor_sync(0xffffffffu, sum, o);
        const float inv = __fdividef(1.f, sum);
        __half* P = (__half*)(smA + OFF_P);
#pragma unroll
        for (int u = 0; u < 10; u++)
            P[p * 168 + l16 + u * 16] = __float2half(vals[u] * inv);
    }
    __syncthreads();

    // --- AV: probs [16x160] x v^T; warp w owns dims [8w, 8w+8) ---
    {
        float acc[4] = {0.f, 0.f, 0.f, 0.f};
#pragma unroll
        for (int kk = 0; kk < 10; kk++) {
            uint32_t af[4];
            ldmx4(af, sb + OFF_P + a_r * 336 + (kk * 16 + a_k) * 2);
            uint32_t bf[2];
            ldmx2t(bf, sb + OFF_V + (kk * 16 + (lane & 15)) * KVROW + warp * 16);
            mma_f16(acc, af, bf);
        }
        const int col = warp * 8 + tg * 2;
        __half2 o0 = __floats2half2_rn(acc[0], acc[1]);
        __half2 o1 = __floats2half2_rn(acc[2], acc[3]);
        __half* op0 = ao + (size_t)(i * HWDIM + jb + g) * DIM + h * HD + col;
        __half* op1 = ao + (size_t)(i * HWDIM + jb + g + 8) * DIM + h * HD + col;
        *(__half2*)op0 = o0;
        *(__half2*)op1 = o1;
    }
}

// ---------------------------------------------------------------------------
extern "C" void kernel_launch(void* const* d_in, const int* in_sizes, int n_in,
                              void* d_out, int out_size)
{
    const float* x      = (const float*)d_in[0];
    const float* qkv_w  = (const float*)d_in[1];
    const float* qkv_b  = (const float*)d_in[2];
    const float* rpb    = (const float*)d_in[3];
    const float* proj_w = (const float*)d_in[4];
    const float* proj_b = (const float*)d_in[5];
    float* out = (float*)d_out;

    __half *qh, *kvh, *xh, *w1h, *ao, *w2h;
    cudaGetSymbolAddress((void**)&qh, g_qh);
    cudaGetSymbolAddress((void**)&kvh, g_kvh);
    cudaGetSymbolAddress((void**)&xh, g_xh);
    cudaGetSymbolAddress((void**)&w1h, g_w1h);
    cudaGetSymbolAddress((void**)&ao, g_ao);
    cudaGetSymbolAddress((void**)&w2h, g_w2h);

    cudaFuncSetAttribute((const void*)gemm_f16<96, 1, 1>,
                         cudaFuncAttributeMaxDynamicSharedMemorySize, GEMM_SMEM_96);
    cudaFuncSetAttribute((const void*)gemm_f16<128, 2, 0>,
                         cudaFuncAttributeMaxDynamicSharedMemorySize, GEMM_SMEM_128);
    cudaFuncSetAttribute((const void*)nat_attn_mma,
                         cudaFuncAttributeMaxDynamicSharedMemorySize, ATTN_SMEM);

    // 0) Zero the split-K target + convert inputs
    zero_out<<<NPIX * DIM / 1024, 256>>>(out);
    cvt_all<<<(N_X + N_W1 + N_W2) / 1024, 256>>>(
        x, qkv_w, proj_w, xh, w1h, w2h);

    // 1) QKV projection: q -> fp16 scaled, k|v -> fp16 (split epilogue)
    gemm_f16<96, 1, 1><<<dim3(QKVN / 96, NPIX / 128), 256, GEMM_SMEM_96>>>(
        xh, w1h, qkv_b, nullptr, kvh, qh, NPIX, QKVN, DIM);

    // 2) Neighborhood attention on tensor cores
    nat_attn_mma<<<dim3(HWDIM / 16, HWDIM, NHEAD), 256, ATTN_SMEM>>>(
        qh, kvh, rpb, ao);

    // 3) Output projection: 128x128 tiles, split-K=2 (400 CTAs)
    gemm_f16<128, 2, 0><<<dim3(DIM / 128, NPIX / 128, 2), 256, GEMM_SMEM_128>>>(
        ao, w2h, proj_b, out, nullptr, nullptr, NPIX, DIM, DIM);
}

// round 17
// speedup vs baseline: 2.1798x; 1.0202x over previous
#include <cuda_runtime.h>
#include <cuda_bf16.h>
#include <cuda_fp16.h>
#include <cstdint>
#include <math.h>

// Problem constants
#define HWDIM 80
#define NPIX  6400
#define DIM   512
#define QKVN  1536
#define NHEAD 8
#define HD    64
#define KWIN  7

// Scratch (allocation-free rule: __device__ globals)
__device__ __half g_qh[(size_t)NPIX * DIM];        // q fp16 (pre-scaled 1/8)
__device__ __half g_kvh[(size_t)NPIX * 1024];      // k|v fp16
__device__ __half g_xh[(size_t)NPIX * DIM];        // x fp16
__device__ __half g_w1h[(size_t)QKVN * DIM];       // qkv_w fp16
__device__ __half g_ao[(size_t)NPIX * DIM];        // attn out fp16
__device__ __half g_w2h[(size_t)DIM * DIM];        // proj_w fp16

#define N_X  (NPIX * DIM)
#define N_W1 (QKVN * DIM)
#define N_W2 (DIM * DIM)

__device__ __forceinline__ uint32_t smem_u32(const void* p) {
    uint32_t a;
    asm("{ .reg .u64 t; cvta.to.shared.u64 t, %1; cvt.u32.u64 %0, t; }"
        : "=r"(a) : "l"(p));
    return a;
}
__device__ __forceinline__ void cp16(uint32_t dst, const void* src) {
    asm volatile("cp.async.cg.shared.global [%0], [%1], 16;"
                 :: "r"(dst), "l"(src));
}
__device__ __forceinline__ void cp_commit() {
    asm volatile("cp.async.commit_group;" ::: "memory");
}
__device__ __forceinline__ void cp_wait0() {
    asm volatile("cp.async.wait_group 0;" ::: "memory");
}
__device__ __forceinline__ void ldmx4(uint32_t* r, uint32_t addr) {
    asm volatile("ldmatrix.sync.aligned.m8n8.x4.shared.b16 {%0,%1,%2,%3}, [%4];"
                 : "=r"(r[0]), "=r"(r[1]), "=r"(r[2]), "=r"(r[3]) : "r"(addr));
}
__device__ __forceinline__ void ldmx2(uint32_t* r, uint32_t addr) {
    asm volatile("ldmatrix.sync.aligned.m8n8.x2.shared.b16 {%0,%1}, [%2];"
                 : "=r"(r[0]), "=r"(r[1]) : "r"(addr));
}
__device__ __forceinline__ void ldmx2t(uint32_t* r, uint32_t addr) {
    asm volatile("ldmatrix.sync.aligned.m8n8.x2.trans.shared.b16 {%0,%1}, [%2];"
                 : "=r"(r[0]), "=r"(r[1]) : "r"(addr));
}
__device__ __forceinline__ void mma_f16(float* c, const uint32_t* a, const uint32_t* b) {
    asm volatile(
        "mma.sync.aligned.m16n8k16.row.col.f32.f16.f16.f32 "
        "{%0,%1,%2,%3}, {%4,%5,%6,%7}, {%8,%9}, {%0,%1,%2,%3};"
        : "+f"(c[0]), "+f"(c[1]), "+f"(c[2]), "+f"(c[3])
        : "r"(a[0]), "r"(a[1]), "r"(a[2]), "r"(a[3]), "r"(b[0]), "r"(b[1]));
}

// ---------------------------------------------------------------------------
// Zero-init for the split-K accumulation target.
// ---------------------------------------------------------------------------
__global__ void __launch_bounds__(256) zero_out(float* __restrict__ p)
{
    const int i = (blockIdx.x * 256 + threadIdx.x) * 4;
    float4 z; z.x = 0.f; z.y = 0.f; z.z = 0.f; z.w = 0.f;
    *(float4*)(p + i) = z;
}

// ---------------------------------------------------------------------------
// Convert inputs: x, qkv_w, proj_w -> plain fp16. One launch.
// ---------------------------------------------------------------------------
__global__ void __launch_bounds__(256) cvt_all(
    const float* __restrict__ x, const float* __restrict__ w1,
    const float* __restrict__ w2,
    __half* __restrict__ xh, __half* __restrict__ w1h,
    __half* __restrict__ w2h)
{
    int i = (blockIdx.x * 256 + threadIdx.x) * 4;
    const float* src;
    __half* dst;
    if (i < N_X)              { src = x + i;             dst = xh + i; }
    else if (i < N_X + N_W1)  { i -= N_X;  src = w1 + i; dst = w1h + i; }
    else                      { i -= N_X + N_W1; src = w2 + i; dst = w2h + i; }

    float4 v = *(const float4*)src;
    __half2 h0 = __floats2half2_rn(v.x, v.y);
    __half2 h1 = __floats2half2_rn(v.z, v.w);
    uint2 o; o.x = *(uint32_t*)&h0; o.y = *(uint32_t*)&h1;
    *(uint2*)dst = o;
}

// ---------------------------------------------------------------------------
// mma.sync fp16 GEMM: C = A @ B^T + bias  (plain fp16 A and B, fp32 accum)
// EPI=0: fp32 C (SK-way split-K via atomics when SK>1).
// EPI=1: QKV split epilogue — cols [0,512)  -> Cq fp16, scaled 1/8 (q),
//                             cols [512,1536) -> C2 fp16 stride 1024 (k|v).
// ---------------------------------------------------------------------------
#define BK 32
#define ROWB 80
#define AMATB (128 * ROWB)

template<int BN, int SK, int EPI>
__global__ void __launch_bounds__(256, 2) gemm_f16(
    const __half* __restrict__ A, const __half* __restrict__ B,
    const float* __restrict__ bias, float* __restrict__ C,
    __half* __restrict__ C2, __half* __restrict__ Cq,
    int M, int N, int K)
{
    constexpr int NI = BN / 32;
    constexpr int BMB = BN * ROWB;
    constexpr int STAGE = AMATB + BMB;
    constexpr int NCH16 = (128 + BN) * 4;
    constexpr int NT4 = (NCH16 + 255) / 256;

    extern __shared__ char smem[];
    const uint32_t sb = smem_u32(smem);
    const int tid = threadIdx.x;
    const int wid = tid >> 5;
    const int lane = tid & 31;
    const int bm = blockIdx.y * 128;
    const int bn = blockIdx.x * BN;
    const int wm = (wid & 1) * 64;
    const int wn = (wid >> 1) * (BN / 4);
    const int kslice = (SK > 1) ? blockIdx.z : 0;
    const int Keff = K / SK;
    const int kbase = kslice * Keff;

    const __half* gA = A + (size_t)bm * K + kbase;
    const __half* gB = B + (size_t)bn * K + kbase;

    float acc[4][NI][4];
#pragma unroll
    for (int mi = 0; mi < 4; mi++)
#pragma unroll
        for (int ni = 0; ni < NI; ni++)
#pragma unroll
            for (int e = 0; e < 4; e++) acc[mi][ni][e] = 0.f;

    const int nch = Keff / BK;

    auto load_stage = [&](int buf, int k0) {
        const uint32_t st = sb + buf * STAGE;
#pragma unroll
        for (int it = 0; it < NT4; it++) {
            const int f = tid + it * 256;
            if (NCH16 % 256 != 0 && f >= NCH16) break;
            const int r = f >> 2;
            const int c = f & 3;
            const __half* src;
            uint32_t dst;
            if (r < 128) { src = gA + (size_t)r * K;
                           dst = st + r * ROWB; }
            else         { src = gB + (size_t)(r - 128) * K;
                           dst = st + AMATB + (r - 128) * ROWB; }
            cp16(dst + c * 16, src + k0 + c * 8);
        }
    };

    const int a_r  = wm + (lane & 15);
    const int a_k  = (lane >> 4) * 8;
    const int b_nr = (lane & 7) + ((lane >> 4) & 1) * 8;
    const int b_k  = ((lane >> 3) & 1) * 8;

    load_stage(0, 0);
    cp_commit();

    for (int ch = 0; ch < nch; ch++) {
        cp_wait0();
        __syncthreads();
        if (ch + 1 < nch) {
            load_stage((ch + 1) & 1, (ch + 1) * BK);
            cp_commit();
        }

        const uint32_t st = sb + (ch & 1) * STAGE;
#pragma unroll
        for (int kk = 0; kk < 2; kk++) {
            uint32_t bf[NI][2];
            const uint32_t bb = st + AMATB + (uint32_t)((kk * 16 + b_k) * 2);
#pragma unroll
            for (int p = 0; p < NI / 2; p++) {
                uint32_t rr[4];
                ldmx4(rr, bb + (wn + p * 16 + b_nr) * ROWB);
                bf[2 * p][0] = rr[0]; bf[2 * p][1] = rr[1];
                bf[2 * p + 1][0] = rr[2]; bf[2 * p + 1][1] = rr[3];
            }
            if (NI & 1) {
                const uint32_t addr = st + AMATB
                    + (uint32_t)((wn + (NI - 1) * 8 + (lane & 7)) * ROWB
                                 + (kk * 16 + b_k) * 2);
                ldmx2(bf[NI - 1], addr);
            }
            const uint32_t ab = st + (uint32_t)(a_r * ROWB + (kk * 16 + a_k) * 2);
#pragma unroll
            for (int mi = 0; mi < 4; mi++) {
                uint32_t af[4];
                ldmx4(af, ab + mi * 16 * ROWB);
#pragma unroll
                for (int ni = 0; ni < NI; ni++)
                    mma_f16(acc[mi][ni], af, bf[ni]);
            }
        }
    }

    const int g = lane >> 2;
    const int tg = lane & 3;
#pragma unroll
    for (int mi = 0; mi < 4; mi++) {
        const int r0 = bm + wm + mi * 16 + g;
#pragma unroll
        for (int ni = 0; ni < NI; ni++) {
            const int col = bn + wn + ni * 8 + tg * 2;
            const float2 bv = *(const float2*)(bias + col);
            const float a0 = acc[mi][ni][0] + bv.x;
            const float a1 = acc[mi][ni][1] + bv.y;
            const float a2 = acc[mi][ni][2] + bv.x;
            const float a3 = acc[mi][ni][3] + bv.y;
            if (EPI == 1) {
                if (col < DIM) {     // q -> fp16 scaled, stride DIM
                    __half2 o0 = __floats2half2_rn(a0 * 0.125f, a1 * 0.125f);
                    __half2 o1 = __floats2half2_rn(a2 * 0.125f, a3 * 0.125f);
                    *(__half2*)(Cq + (size_t)r0 * DIM + col) = o0;
                    *(__half2*)(Cq + (size_t)(r0 + 8) * DIM + col) = o1;
                } else {             // k|v -> fp16, stride 1024
                    const int c2 = col - DIM;
                    __half2 o0 = __floats2half2_rn(a0, a1);
                    __half2 o1 = __floats2half2_rn(a2, a3);
                    *(__half2*)(C2 + (size_t)r0 * 1024 + c2) = o0;
                    *(__half2*)(C2 + (size_t)(r0 + 8) * 1024 + c2) = o1;
                }
            } else if (SK == 1) {
                float2 o0, o1;
                o0.x = a0; o0.y = a1;
                o1.x = a2; o1.y = a3;
                *(float2*)(C + (size_t)r0 * N + col) = o0;
                *(float2*)(C + (size_t)(r0 + 8) * N + col) = o1;
            } else {
                const float bx = (kslice == 0) ? 0.f : bv.x;
                const float by = (kslice == 0) ? 0.f : bv.y;
                float* p0 = C + (size_t)r0 * N + col;
                float* p1 = C + (size_t)(r0 + 8) * N + col;
                atomicAdd(p0,     a0 - bx);
                atomicAdd(p0 + 1, a1 - by);
                atomicAdd(p1,     a2 - bx);
                atomicAdd(p1 + 1, a3 - by);
            }
        }
    }
}

#define GEMM_SMEM_96  (2 * (AMATB + 96 * ROWB))
#define GEMM_SMEM_128 (2 * (AMATB + 128 * ROWB))

// ---------------------------------------------------------------------------
// Neighborhood attention via tensor cores, K/V sharing ONE smem buffer.
// Block = 16 pixels (one row i) x 1 head; grid (5, 80, 8); 256 threads.
// Phases: load K+Q -> QK^T -> sync -> issue V load into K's buffer ->
//         softmax (overlaps V load) -> wait -> AV.
// smem 41.25 KB -> 5 CTAs/SM.
// ---------------------------------------------------------------------------
#define NU 160
#define KVROW 144
#define OFF_KV 0                              // K, then V (23040 B)
#define OFF_Q  (NU * KVROW)                   // 23040 (2304 B)
#define OFF_P  (OFF_Q + 16 * KVROW)           // 25344 (5376 B)
#define OFF_S  (OFF_P + 16 * 336)             // 30720 (10240 B)
#define OFF_RO (OFF_S + 16 * NU * 4)          // 40960 (640 B)
#define OFF_AC (OFF_RO + NU * 4)              // 41600 (640 B)
#define ATTN_SMEM (OFF_AC + NU * 4)           // 42240

__global__ void __launch_bounds__(256) nat_attn_mma(
    const __half* __restrict__ qh, const __half* __restrict__ kvh,
    const float* __restrict__ rpb,
    __half* __restrict__ ao)
{
    extern __shared__ char smA[];
    const uint32_t sb = smem_u32(smA);

    const int tid = threadIdx.x;
    const int warp = tid >> 5;
    const int lane = tid & 31;
    const int jb = blockIdx.x * 16;
    const int i = blockIdx.y;
    const int h = blockIdx.z;

    const int sh = min(max(i - 3, 0), HWDIM - KWIN);
    const int cmin = min(max(jb - 3, 0), HWDIM - KWIN);
    const int cmax = min(max(jb + 12, 0), HWDIM - KWIN) + 6;
    const int wb = cmax - cmin + 1;            // 19..22
    const int dh0 = sh - i + 6;

    // --- tables: per-union-column gmem row offset (clamped) + (a,c) LUT ---
    uint32_t* RO = (uint32_t*)(smA + OFF_RO);
    uint32_t* AC = (uint32_t*)(smA + OFF_AC);
    if (tid < NU) {
        const int s = tid;
        int a = (s * 2979) >> 16;              // s / 22
        const int c = s - 22 * a;
        AC[s] = (uint32_t)(a * 32 + c);        // unclamped for masking
        if (a > 6) a = 6;                      // clamp pad rows to valid data
        const int ccl = min(c, wb - 1);
        RO[s] = (uint32_t)(((sh + a) * HWDIM + cmin + ccl) * 1024 + h * HD);
    }
    __syncthreads();

    // --- stage K (160 rows x 64 fp16) and q (16 rows) via cp.async ---
#pragma unroll
    for (int it = 0; it < 5; it++) {
        const int idx = tid + it * 256;        // 0..1279
        const int row = idx >> 3;
        const int ch = idx & 7;
        cp16(sb + OFF_KV + row * KVROW + ch * 16, kvh + RO[row] + ch * 8);
    }
    if (tid < 128) {
        const int r = tid >> 3, ch = tid & 7;
        cp16(sb + OFF_Q + r * KVROW + ch * 16,
             qh + (size_t)(i * HWDIM + jb + r) * DIM + h * HD + ch * 8);
    }
    cp_commit();
    cp_wait0();
    __syncthreads();

    // --- QK^T: warp w covers n-cols [16w,16w+16) + (w<4: [128+8w, +8)) ---
    const int g = lane >> 2;
    const int tg = lane & 3;
    const int a_r = lane & 15;
    const int a_k = (lane >> 4) * 8;
    const int b_nr = (lane & 7) + ((lane >> 4) & 1) * 8;
    const int b_k = ((lane >> 3) & 1) * 8;

    {
        float accP[2][4] = {{0.f}}, accE[4] = {0.f};
#pragma unroll
        for (int kk = 0; kk < 4; kk++) {
            uint32_t af[4];
            ldmx4(af, sb + OFF_Q + a_r * KVROW + (kk * 16 + a_k) * 2);
            uint32_t bp[4];
            ldmx4(bp, sb + OFF_KV + (16 * warp + b_nr) * KVROW + (kk * 16 + b_k) * 2);
            uint32_t b0[2] = {bp[0], bp[1]}, b1[2] = {bp[2], bp[3]};
            mma_f16(accP[0], af, b0);
            mma_f16(accP[1], af, b1);
            if (warp < 4) {
                uint32_t be[2];
                ldmx2(be, sb + OFF_KV + (128 + 8 * warp + (lane & 7)) * KVROW
                          + (kk * 16 + b_k) * 2);
                mma_f16(accE, af, be);
            }
        }
        float* S = (float*)(smA + OFF_S);
#pragma unroll
        for (int ni = 0; ni < 2; ni++) {
            const int cb = 16 * warp + ni * 8 + tg * 2;
            float2 t0; t0.x = accP[ni][0]; t0.y = accP[ni][1];
            float2 t1; t1.x = accP[ni][2]; t1.y = accP[ni][3];
            *(float2*)&S[g * NU + cb] = t0;
            *(float2*)&S[(g + 8) * NU + cb] = t1;
        }
        if (warp < 4) {
            const int cb = 128 + 8 * warp + tg * 2;
            float2 t0; t0.x = accE[0]; t0.y = accE[1];
            float2 t1; t1.x = accE[2]; t1.y = accE[3];
            *(float2*)&S[g * NU + cb] = t0;
            *(float2*)&S[(g + 8) * NU + cb] = t1;
        }
    }
    __syncthreads();   // all K reads done; S visible

    // --- issue V load into the SAME buffer (overlaps with softmax) ---
#pragma unroll
    for (int it = 0; it < 5; it++) {
        const int idx = tid + it * 256;
        const int row = idx >> 3;
        const int ch = idx & 7;
        cp16(sb + OFF_KV + row * KVROW + ch * 16, kvh + RO[row] + 512 + ch * 8);
    }
    cp_commit();

    // --- bias + mask + softmax: 16 teams of 16 lanes (one pixel each) ---
    {
        const int p = tid >> 4;
        const int l16 = tid & 15;
        const int jp = jb + p;
        const int swp = min(max(jp - 3, 0), HWDIM - KWIN);
        const float* S = (const float*)(smA + OFF_S);
        const float* rpbase = rpb + h * 169 + dh0 * 13;
        float vals[10];
        float mx = -1e30f;
#pragma unroll
        for (int u = 0; u < 10; u++) {
            const int col = l16 + u * 16;
            const uint32_t ac = AC[col];
            const int a = ac >> 5;
            const int c = ac & 31;
            const int cw = cmin + c;
            const int d = cw - swp;
            const bool ok = (a < 7) && (c < wb) && (d >= 0) && (d <= 6);
            float s = -1e30f;
            if (ok) s = S[p * NU + col] + rpbase[a * 13 + (cw - jp + 6)];
            vals[u] = s;
            mx = fmaxf(mx, s);
        }
#pragma unroll
        for (int o = 8; o; o >>= 1)
            mx = fmaxf(mx, __shfl_xor_sync(0xffffffffu, mx, o));
        float sum = 0.f;
#pragma unroll
        for (int u = 0; u < 10; u++) {
            vals[u] = __expf(vals[u] - mx);
            sum += vals[u];
        }
#pragma unroll
        for (int o = 8; o; o >>= 1)
            sum += __shfl_xor_sync(0xffffffffu, sum, o);
        const float inv = __fdividef(1.f, sum);
        __half* P = (__half*)(smA + OFF_P);
#pragma unroll
        for (int u = 0; u < 10; u++)
            P[p * 168 + l16 + u * 16] = __float2half(vals[u] * inv);
    }
    cp_wait0();
    __syncthreads();   // V staged; P visible

    // --- AV: probs [16x160] x v^T; warp w owns dims [8w, 8w+8) ---
    {
        float acc[4] = {0.f, 0.f, 0.f, 0.f};
#pragma unroll
        for (int kk = 0; kk < 10; kk++) {
            uint32_t af[4];
            ldmx4(af, sb + OFF_P + a_r * 336 + (kk * 16 + a_k) * 2);
            uint32_t bf[2];
            ldmx2t(bf, sb + OFF_KV + (kk * 16 + (lane & 15)) * KVROW + warp * 16);
            mma_f16(acc, af, bf);
        }
        const int col = warp * 8 + tg * 2;
        __half2 o0 = __floats2half2_rn(acc[0], acc[1]);
        __half2 o1 = __floats2half2_rn(acc[2], acc[3]);
        __half* op0 = ao + (size_t)(i * HWDIM + jb + g) * DIM + h * HD + col;
        __half* op1 = ao + (size_t)(i * HWDIM + jb + g + 8) * DIM + h * HD + col;
        *(__half2*)op0 = o0;
        *(__half2*)op1 = o1;
    }
}

// ---------------------------------------------------------------------------
extern "C" void kernel_launch(void* const* d_in, const int* in_sizes, int n_in,
                              void* d_out, int out_size)
{
    const float* x      = (const float*)d_in[0];
    const float* qkv_w  = (const float*)d_in[1];
    const float* qkv_b  = (const float*)d_in[2];
    const float* rpb    = (const float*)d_in[3];
    const float* proj_w = (const float*)d_in[4];
    const float* proj_b = (const float*)d_in[5];
    float* out = (float*)d_out;

    __half *qh, *kvh, *xh, *w1h, *ao, *w2h;
    cudaGetSymbolAddress((void**)&qh, g_qh);
    cudaGetSymbolAddress((void**)&kvh, g_kvh);
    cudaGetSymbolAddress((void**)&xh, g_xh);
    cudaGetSymbolAddress((void**)&w1h, g_w1h);
    cudaGetSymbolAddress((void**)&ao, g_ao);
    cudaGetSymbolAddress((void**)&w2h, g_w2h);

    cudaFuncSetAttribute((const void*)gemm_f16<96, 1, 1>,
                         cudaFuncAttributeMaxDynamicSharedMemorySize, GEMM_SMEM_96);
    cudaFuncSetAttribute((const void*)gemm_f16<128, 2, 0>,
                         cudaFuncAttributeMaxDynamicSharedMemorySize, GEMM_SMEM_128);
    cudaFuncSetAttribute((const void*)nat_attn_mma,
                         cudaFuncAttributeMaxDynamicSharedMemorySize, ATTN_SMEM);

    // 0) Zero the split-K target + convert inputs
    zero_out<<<NPIX * DIM / 1024, 256>>>(out);
    cvt_all<<<(N_X + N_W1 + N_W2) / 1024, 256>>>(
        x, qkv_w, proj_w, xh, w1h, w2h);

    // 1) QKV projection: q -> fp16 scaled, k|v -> fp16 (split epilogue)
    gemm_f16<96, 1, 1><<<dim3(QKVN / 96, NPIX / 128), 256, GEMM_SMEM_96>>>(
        xh, w1h, qkv_b, nullptr, kvh, qh, NPIX, QKVN, DIM);

    // 2) Neighborhood attention on tensor cores (shared K/V buffer)
    nat_attn_mma<<<dim3(HWDIM / 16, HWDIM, NHEAD), 256, ATTN_SMEM>>>(
        qh, kvh, rpb, ao);

    // 3) Output projection: 128x128 tiles, split-K=2 (400 CTAs)
    gemm_f16<128, 2, 0><<<dim3(DIM / 128, NPIX / 128, 2), 256, GEMM_SMEM_128>>>(
        ao, w2h, proj_b, out, nullptr, nullptr, NPIX, DIM, DIM);
}